// round 1
// baseline (speedup 1.0000x reference)
#include <cuda_runtime.h>
#include <cuda_bf16.h>
#include <cstdint>

// ---------------------------------------------------------------------------
// DWT_Features: fold 3-level db4 DWT (linear) into conv weights, then 4x
// fp32 GEMM (M=2048, N=128, K=4096) with packed fma.rn.f32x2.
// ---------------------------------------------------------------------------

#define B_DIM    2048
#define SW_DIM   4
#define SWS_DIM  64
#define HW2      64          // 8*8
#define KF       128         // filters per subwindow
#define DWT_LEN  84
#define KDIM     4096        // SWS_DIM * HW2 (reduction length per s)
#define OUTC     512         // SW_DIM * KF

// db4 analysis filters (dec_lo / dec_hi). Reference uses reversed filters with
// correlation, i.e. y[j] = sum_i xpad[2j+i] * dec[7-i].
__constant__ float c_dec_lo[8] = {
    -0.010597401784997278f,  0.032883011666982945f,  0.030841381835986965f,
    -0.18703481171888114f,  -0.02798376941698385f,   0.6308807679295904f,
     0.7148465705525415f,    0.23037781330885523f };
__constant__ float c_dec_hi[8] = {
    -0.23037781330885523f,   0.7148465705525415f,   -0.6308807679295904f,
    -0.02798376941698385f,   0.18703481171888114f,   0.030841381835986965f,
    -0.032883011666982945f, -0.010597401784997278f };

// M[t][tau] : coeff_t = sum_tau M[t,tau] * x_tau   (84 x 64)
__device__ float g_M[DWT_LEN * SWS_DIM];
// W_eff transposed: [s][j][k]  (j = tau*64 + hw), 4*4096*128 floats = 8 MB
__device__ __align__(16) float g_Weff[SW_DIM * KDIM * KF];

// ---------------------------------------------------------------------------
// One analysis level, exactly matching the reference _dwt_level:
//   outsize = (N+7)//2 ; p = 2*(outsize-1) - N + 8
//   if p odd: append ONE zero at the end (len Nz = N+1), then reflect-pad
//   p//2 (=6) on both sides; stride-2 correlation with dec[7-i].
// ---------------------------------------------------------------------------
__device__ void dwt_level(const float* x, int N, float* lo, float* hi) {
    int outsize = (N + 7) >> 1;
    int p = 2 * (outsize - 1) - N + 8;      // 12 or 13 for our sizes
    int Nz = N + (p & 1);                   // zero-extended length
    for (int j = 0; j < outsize; j++) {
        float sl = 0.f, sh = 0.f;
        #pragma unroll
        for (int i = 0; i < 8; i++) {
            int idx = 2 * j + i - 6;        // p/2 == 6 always here
            if (idx < 0) idx = -idx;                    // reflect left
            if (idx > Nz - 1) idx = 2 * (Nz - 1) - idx; // reflect right
            float v = (idx < N) ? x[idx] : 0.f;         // appended zero
            sl += v * c_dec_lo[7 - i];
            sh += v * c_dec_hi[7 - i];
        }
        lo[j] = sl; hi[j] = sh;
    }
}

// Build the 84x64 DWT matrix by transforming the identity. 64 threads.
__global__ void k_build_dwt() {
    int tau = threadIdx.x;
    if (tau >= SWS_DIM) return;
    float x0[64], lo1[35], lo2[21], out[DWT_LEN];
    #pragma unroll
    for (int i = 0; i < 64; i++) x0[i] = (i == tau) ? 1.f : 0.f;
    dwt_level(x0, 64, lo1, out + 14);   // hi1 -> rows 14..48
    dwt_level(lo1, 35, lo2, out + 49);  // hi2 -> rows 49..69
    dwt_level(lo2, 21, out, out + 70);  // lo3 -> rows 0..13, hi3 -> 70..83
    for (int t = 0; t < DWT_LEN; t++) g_M[t * 64 + tau] = out[t];
}

// ---------------------------------------------------------------------------
// W_eff[s][j][k] = sum_t M[t][tau] * cw[s,k,t,hw],  j = tau*64 + hw.
// One block per (s,k). smem: M (21.5KB) + weight slice (21.5KB).
// ---------------------------------------------------------------------------
__global__ void k_weff(const float* __restrict__ cw) {
    int sk = blockIdx.x;                 // 0..511
    int s = sk >> 7, k = sk & 127;
    __shared__ float Ms[DWT_LEN * 64];
    __shared__ float Ws[DWT_LEN * 64];
    const float* src = cw + (size_t)sk * (DWT_LEN * HW2);
    for (int i = threadIdx.x; i < DWT_LEN * 64; i += blockDim.x) {
        Ms[i] = g_M[i];
        Ws[i] = src[i];
    }
    __syncthreads();
    for (int j = threadIdx.x; j < KDIM; j += blockDim.x) {
        int tau = j >> 6, hw = j & 63;
        float acc = 0.f;
        #pragma unroll 4
        for (int t = 0; t < DWT_LEN; t++)
            acc += Ms[t * 64 + tau] * Ws[t * 64 + hw];
        g_Weff[((size_t)s * KDIM + j) * KF + k] = acc;
    }
}

// ---------------------------------------------------------------------------
// Packed fp32x2 helpers (Blackwell FFMA2 — not emitted by ptxas from C++).
// ---------------------------------------------------------------------------
__device__ __forceinline__ unsigned long long pack2(float x, float y) {
    unsigned long long r;
    asm("mov.b64 %0, {%1, %2};" : "=l"(r) : "f"(x), "f"(y));
    return r;
}
__device__ __forceinline__ void fma2(unsigned long long& d,
                                     unsigned long long a,
                                     unsigned long long b) {
    asm("fma.rn.f32x2 %0, %1, %2, %3;" : "=l"(d) : "l"(a), "l"(b), "l"(d));
}
__device__ __forceinline__ void unpack2(unsigned long long v, float& x, float& y) {
    asm("mov.b64 {%0, %1}, %2;" : "=f"(x), "=f"(y) : "l"(v));
}

// ---------------------------------------------------------------------------
// GEMM: out[b, s*128 + n] = leaky(bias + sum_j x[b,s,j] * Weff[s,j,n])
// Tiles: BM=64, BN=64, BK=32. 256 threads, 4x4 per thread (2x f32x2 pairs).
// grid.x = 8 (s*2 + ntile), grid.y = 32 (m tiles).
// ---------------------------------------------------------------------------
#define BM 64
#define BN 64
#define BK 32

__global__ __launch_bounds__(256)
void k_gemm(const float* __restrict__ x, const float* __restrict__ bias,
            float* __restrict__ out) {
    const int s  = blockIdx.x >> 1;
    const int n0 = (blockIdx.x & 1) * BN;     // within the 128 cols of this s
    const int m0 = blockIdx.y * BM;

    const float* A  = x + (size_t)m0 * (SW_DIM * KDIM) + (size_t)s * KDIM;
    const float* Bp = g_Weff + (size_t)s * KDIM * KF + n0;

    __shared__ __align__(16) float As[BK][BM];
    __shared__ __align__(16) float Bs[BK][BN];

    const int tid = threadIdx.x;
    const int tx = tid & 15;        // 16 cols of threads -> 4 output cols each
    const int ty = tid >> 4;        // 16 rows of threads -> 4 output rows each

    unsigned long long acc[4][2];
    #pragma unroll
    for (int i = 0; i < 4; i++) { acc[i][0] = 0ull; acc[i][1] = 0ull; }

    for (int k0 = 0; k0 < KDIM; k0 += BK) {
        // Load A tile: 64 rows x 32 cols, transposed into As[col][row]
        #pragma unroll
        for (int it = 0; it < 2; it++) {
            int idx = tid + it * 256;           // 0..511 float4 slots
            int row = idx >> 3;
            int c4  = (idx & 7) << 2;
            float4 v = *(const float4*)(A + (size_t)row * (SW_DIM * KDIM) + k0 + c4);
            As[c4 + 0][row] = v.x;
            As[c4 + 1][row] = v.y;
            As[c4 + 2][row] = v.z;
            As[c4 + 3][row] = v.w;
        }
        // Load B tile: 32 rows x 64 cols (row-major, coalesced float4)
        #pragma unroll
        for (int it = 0; it < 2; it++) {
            int idx = tid + it * 256;
            int row = idx >> 4;                 // 0..31
            int c4  = (idx & 15) << 2;
            *(float4*)&Bs[row][c4] =
                *(const float4*)(Bp + (size_t)(k0 + row) * KF + c4);
        }
        __syncthreads();

        #pragma unroll
        for (int kk = 0; kk < BK; kk++) {
            float4 av = *(const float4*)&As[kk][ty << 2];
            ulonglong2 bv = *(const ulonglong2*)&Bs[kk][tx << 2];
            unsigned long long a0 = pack2(av.x, av.x);
            unsigned long long a1 = pack2(av.y, av.y);
            unsigned long long a2 = pack2(av.z, av.z);
            unsigned long long a3 = pack2(av.w, av.w);
            fma2(acc[0][0], a0, bv.x); fma2(acc[0][1], a0, bv.y);
            fma2(acc[1][0], a1, bv.x); fma2(acc[1][1], a1, bv.y);
            fma2(acc[2][0], a2, bv.x); fma2(acc[2][1], a2, bv.y);
            fma2(acc[3][0], a3, bv.x); fma2(acc[3][1], a3, bv.y);
        }
        __syncthreads();
    }

    // Epilogue: bias + leaky relu (slope 0.01), write out[b, s*128 + col]
    const int colg = s * KF + n0 + (tx << 2);   // global output column base
    float b0 = bias[colg + 0], b1 = bias[colg + 1];
    float b2 = bias[colg + 2], b3 = bias[colg + 3];
    #pragma unroll
    for (int i = 0; i < 4; i++) {
        float r0, r1, r2, r3;
        unpack2(acc[i][0], r0, r1);
        unpack2(acc[i][1], r2, r3);
        r0 += b0; r1 += b1; r2 += b2; r3 += b3;
        r0 = (r0 > 0.f) ? r0 : 0.01f * r0;
        r1 = (r1 > 0.f) ? r1 : 0.01f * r1;
        r2 = (r2 > 0.f) ? r2 : 0.01f * r2;
        r3 = (r3 > 0.f) ? r3 : 0.01f * r3;
        float* o = out + (size_t)(m0 + (ty << 2) + i) * OUTC + colg;
        o[0] = r0; o[1] = r1; o[2] = r2; o[3] = r3;
    }
}

// ---------------------------------------------------------------------------
extern "C" void kernel_launch(void* const* d_in, const int* in_sizes, int n_in,
                              void* d_out, int out_size) {
    const float* x    = (const float*)d_in[0];   // [2048,1,256,8,8]
    const float* cw   = (const float*)d_in[1];   // [4,128,84,8,8]
    const float* bias = (const float*)d_in[2];   // [4,128]
    float* out = (float*)d_out;                  // [2048,512]

    k_build_dwt<<<1, 64>>>();
    k_weff<<<SW_DIM * KF, 256>>>(cw);
    dim3 grid(8, B_DIM / BM);
    k_gemm<<<grid, 256>>>(x, bias, out);
}

// round 3
// speedup vs baseline: 2.4330x; 2.4330x over previous
#include <cuda_runtime.h>
#include <cuda_bf16.h>
#include <cstdint>

// ---------------------------------------------------------------------------
// DWT_Features on GB300 (sm_103 PTX target -> no tcgen05.ld; use mma.sync):
//   1) fold 3-level db4 DWT (linear) into conv weights -> W_eff (bf16 hi/lo)
//   2) GEMM out[b, s*128+n] = leaky(bias + sum_k x[b,s,k] * Weff[s,n,k])
//      via HMMA bf16 3-pass split (Ah*Bh + Ah*Bl + Al*Bh), fp32 accum.
// ---------------------------------------------------------------------------

#define B_DIM    2048
#define SW_DIM   4
#define KF       128
#define DWT_LEN  84
#define KDIM     4096
#define OUTC     512
#define BK       64            // K per chunk (bf16)
#define NCHUNK   (KDIM / BK)   // 64
#define BM       64            // rows per CTA

// smem: padded rows 72 bf16 = 144 B (conflict-free ldmatrix)
#define ROWB     144
#define OFF_AH   0
#define OFF_AL   9216          // 64*144
#define OFF_BH   18432
#define OFF_BL   36864         // + 128*144
#define STAGE    55296
#define DSMEM    (2 * STAGE)   // 110592

__constant__ float c_dec_lo[8] = {
    -0.010597401784997278f,  0.032883011666982945f,  0.030841381835986965f,
    -0.18703481171888114f,  -0.02798376941698385f,   0.6308807679295904f,
     0.7148465705525415f,    0.23037781330885523f };
__constant__ float c_dec_hi[8] = {
    -0.23037781330885523f,   0.7148465705525415f,   -0.6308807679295904f,
    -0.02798376941698385f,   0.18703481171888114f,   0.030841381835986965f,
    -0.032883011666982945f, -0.010597401784997278f };

__device__ float g_M[DWT_LEN * 64];                               // 84 x 64
__device__ __align__(16) __nv_bfloat16 g_Wh[SW_DIM * KF * KDIM];  // [s*128+n][k]
__device__ __align__(16) __nv_bfloat16 g_Wl[SW_DIM * KF * KDIM];

// ---------------------------------------------------------------------------
__device__ __forceinline__ uint32_t smem_u32(const void* p) {
    uint32_t a;
    asm("{ .reg .u64 t; cvta.to.shared.u64 t, %1; cvt.u32.u64 %0, t; }"
        : "=r"(a) : "l"(p));
    return a;
}
__device__ __forceinline__ void cp16(uint32_t dst, const void* src) {
    asm volatile("cp.async.cg.shared.global [%0], [%1], 16;"
                 :: "r"(dst), "l"(src) : "memory");
}
__device__ __forceinline__ void ldsm4(uint32_t* r, uint32_t addr) {
    asm volatile("ldmatrix.sync.aligned.m8n8.x4.shared.b16 {%0,%1,%2,%3}, [%4];"
                 : "=r"(r[0]), "=r"(r[1]), "=r"(r[2]), "=r"(r[3]) : "r"(addr));
}
__device__ __forceinline__ void mma_bf16(float* c, const uint32_t* a,
                                         const uint32_t* b) {
    asm volatile(
        "mma.sync.aligned.m16n8k16.row.col.f32.bf16.bf16.f32 "
        "{%0,%1,%2,%3}, {%4,%5,%6,%7}, {%8,%9}, {%0,%1,%2,%3};"
        : "+f"(c[0]), "+f"(c[1]), "+f"(c[2]), "+f"(c[3])
        : "r"(a[0]), "r"(a[1]), "r"(a[2]), "r"(a[3]), "r"(b[0]), "r"(b[1]));
}

// ---------------------------------------------------------------------------
// DWT matrix build (mirrors reference _dwt_level exactly; verified R1).
// ---------------------------------------------------------------------------
__device__ void dwt_lvl(const float* x, int N, float* lo, int ls,
                        float* hi, int hs) {
    int outsize = (N + 7) >> 1;
    int p = 2 * (outsize - 1) - N + 8;
    int Nz = N + (p & 1);
    for (int j = 0; j < outsize; j++) {
        float sl = 0.f, sh = 0.f;
        #pragma unroll
        for (int i = 0; i < 8; i++) {
            int idx = 2 * j + i - 6;
            if (idx < 0) idx = -idx;
            if (idx > Nz - 1) idx = 2 * (Nz - 1) - idx;
            float v = (idx < N) ? x[idx] : 0.f;
            sl += v * c_dec_lo[7 - i];
            sh += v * c_dec_hi[7 - i];
        }
        lo[j * ls] = sl; hi[j * hs] = sh;
    }
}

__global__ void k_build_dwt() {
    __shared__ float sx[64][68], s1[64][36], s2[64][24];
    int tau = threadIdx.x;
    if (tau >= 64) return;
    #pragma unroll
    for (int i = 0; i < 64; i++) sx[tau][i] = (i == tau) ? 1.f : 0.f;
    dwt_lvl(&sx[tau][0], 64, &s1[tau][0], 1, g_M + 14 * 64 + tau, 64);
    dwt_lvl(&s1[tau][0], 35, &s2[tau][0], 1, g_M + 49 * 64 + tau, 64);
    dwt_lvl(&s2[tau][0], 21, g_M + tau, 64, g_M + 70 * 64 + tau, 64);
}

// ---------------------------------------------------------------------------
// W_eff[s][n][j] = sum_t M[t][tau] * cw[s,n,t,hw],  j = tau*64+hw; bf16 split.
// ---------------------------------------------------------------------------
__global__ void k_weff(const float* __restrict__ cw) {
    int sk = blockIdx.x;                       // s*128 + n
    __shared__ float Ms[DWT_LEN * 64];
    __shared__ float Ws[DWT_LEN * 64];
    const float* src = cw + (size_t)sk * (DWT_LEN * 64);
    for (int i = threadIdx.x; i < DWT_LEN * 64; i += blockDim.x) {
        Ms[i] = g_M[i];
        Ws[i] = src[i];
    }
    __syncthreads();
    for (int j = threadIdx.x; j < KDIM; j += blockDim.x) {
        int tau = j >> 6, hw = j & 63;
        float acc = 0.f;
        #pragma unroll 4
        for (int t = 0; t < DWT_LEN; t++)
            acc += Ms[t * 64 + tau] * Ws[t * 64 + hw];
        __nv_bfloat16 wh = __float2bfloat16(acc);
        float wl = acc - __bfloat162float(wh);
        size_t o = (size_t)sk * KDIM + j;
        g_Wh[o] = wh;
        g_Wl[o] = __float2bfloat16(wl);
    }
}

// ---------------------------------------------------------------------------
// HMMA GEMM. CTA = (s, 64-row m-tile). 8 warps = 2(M) x 4(N); warp tile 32x32.
// ---------------------------------------------------------------------------
#define ISSUE_B(K0, STOFF) do {                                              \
    uint32_t _st = sbase + (STOFF);                                          \
    _Pragma("unroll")                                                        \
    for (int _it = 0; _it < 4; _it++) {                                      \
        int _idx = tid + _it * 256;                                          \
        int _n = _idx >> 3, _seg = _idx & 7;                                 \
        uint32_t _d = _n * ROWB + _seg * 16;                                 \
        size_t _g = (size_t)_n * KDIM + (K0) + _seg * 8;                     \
        cp16(_st + OFF_BH + _d, WhB + _g);                                   \
        cp16(_st + OFF_BL + _d, WlB + _g);                                   \
    }                                                                        \
    asm volatile("cp.async.commit_group;" ::: "memory");                     \
} while (0)

#define LDG_A(K0) do {                                                       \
    _Pragma("unroll")                                                        \
    for (int _it = 0; _it < 4; _it++) {                                      \
        int _idx = tid + _it * 256;                                          \
        int _row = _idx >> 4, _seg = _idx & 15;                              \
        areg[_it] = *(const float4*)(Abase +                                 \
            (size_t)_row * (SW_DIM * KDIM) + (K0) + _seg * 4);               \
    }                                                                        \
} while (0)

#define STS_A(STOFF) do {                                                    \
    char* _pb = sm + (STOFF);                                                \
    _Pragma("unroll")                                                        \
    for (int _it = 0; _it < 4; _it++) {                                      \
        int _idx = tid + _it * 256;                                          \
        int _row = _idx >> 4, _seg = _idx & 15;                              \
        float4 _v = areg[_it];                                               \
        __nv_bfloat162 _h01 = __float22bfloat162_rn(make_float2(_v.x, _v.y));\
        __nv_bfloat162 _h23 = __float22bfloat162_rn(make_float2(_v.z, _v.w));\
        float2 _f01 = __bfloat1622float2(_h01);                              \
        float2 _f23 = __bfloat1622float2(_h23);                              \
        __nv_bfloat162 _l01 = __float22bfloat162_rn(                         \
            make_float2(_v.x - _f01.x, _v.y - _f01.y));                      \
        __nv_bfloat162 _l23 = __float22bfloat162_rn(                         \
            make_float2(_v.z - _f23.x, _v.w - _f23.y));                      \
        uint32_t _o = _row * ROWB + _seg * 8;                                \
        *(uint2*)(_pb + OFF_AH + _o) =                                       \
            make_uint2(*(uint32_t*)&_h01, *(uint32_t*)&_h23);                \
        *(uint2*)(_pb + OFF_AL + _o) =                                       \
            make_uint2(*(uint32_t*)&_l01, *(uint32_t*)&_l23);                \
    }                                                                        \
} while (0)

__global__ void __launch_bounds__(256)
k_gemm(const float* __restrict__ x, const float* __restrict__ bias,
       float* __restrict__ out) {
    extern __shared__ char sm[];
    const int tid = threadIdx.x;
    const int wid = tid >> 5, lid = tid & 31;
    const int s = blockIdx.x;
    const int m0 = blockIdx.y * BM;
    const int wm = wid & 1, wn = wid >> 1;

    const uint32_t sbase = smem_u32(sm);
    const float* Abase = x + (size_t)m0 * (SW_DIM * KDIM) + (size_t)s * KDIM;
    const __nv_bfloat16* WhB = g_Wh + (size_t)s * KF * KDIM;
    const __nv_bfloat16* WlB = g_Wl + (size_t)s * KF * KDIM;

    // per-lane ldmatrix address components
    const int q = lid >> 3, r = lid & 7;
    const uint32_t laneA = (wm * 32 + (q & 1) * 8 + r) * ROWB + (q >> 1) * 16;
    const uint32_t laneB = (wn * 32 + (q >> 1) * 8 + r) * ROWB + (q & 1) * 16;

    float acc[2][4][4];
    #pragma unroll
    for (int a = 0; a < 2; a++)
        #pragma unroll
        for (int b = 0; b < 4; b++)
            #pragma unroll
            for (int c = 0; c < 4; c++) acc[a][b][c] = 0.f;

    float4 areg[4];

    // prologue
    ISSUE_B(0, 0);
    ISSUE_B(BK, STAGE);
    LDG_A(0);

    for (int i = 0; i < NCHUNK; i++) {
        const uint32_t stOff = (i & 1) ? STAGE : 0;
        STS_A(stOff);
        if (i < NCHUNK - 1)
            asm volatile("cp.async.wait_group 1;" ::: "memory");
        else
            asm volatile("cp.async.wait_group 0;" ::: "memory");
        __syncthreads();
        if (i + 1 < NCHUNK) LDG_A((i + 1) * BK);

        const uint32_t st = sbase + stOff;
        #pragma unroll
        for (int ks = 0; ks < 4; ks++) {
            const uint32_t ka = ks * 32;
            uint32_t A0h[4], A1h[4], A0l[4], A1l[4];
            uint32_t B0h[4], B1h[4], B0l[4], B1l[4];
            ldsm4(A0h, st + OFF_AH + laneA + ka);
            ldsm4(A1h, st + OFF_AH + laneA + ka + 16 * ROWB);
            ldsm4(A0l, st + OFF_AL + laneA + ka);
            ldsm4(A1l, st + OFF_AL + laneA + ka + 16 * ROWB);
            ldsm4(B0h, st + OFF_BH + laneB + ka);
            ldsm4(B1h, st + OFF_BH + laneB + ka + 16 * ROWB);
            ldsm4(B0l, st + OFF_BL + laneB + ka);
            ldsm4(B1l, st + OFF_BL + laneB + ka + 16 * ROWB);
            #pragma unroll
            for (int nf = 0; nf < 4; nf++) {
                const uint32_t* bh = ((nf & 2) ? B1h : B0h) + (nf & 1) * 2;
                const uint32_t* bl = ((nf & 2) ? B1l : B0l) + (nf & 1) * 2;
                mma_bf16(acc[0][nf], A0h, bh);
                mma_bf16(acc[1][nf], A1h, bh);
                mma_bf16(acc[0][nf], A0h, bl);
                mma_bf16(acc[1][nf], A1h, bl);
                mma_bf16(acc[0][nf], A0l, bh);
                mma_bf16(acc[1][nf], A1l, bh);
            }
        }
        __syncthreads();
        if (i + 2 < NCHUNK) ISSUE_B((i + 2) * BK, stOff);
    }

    // epilogue: bias + leaky relu
    const int g = lid >> 2, tc = lid & 3;
    #pragma unroll
    for (int mf = 0; mf < 2; mf++) {
        const int row = m0 + wm * 32 + mf * 16 + g;
        #pragma unroll
        for (int nf = 0; nf < 4; nf++) {
            const int col = s * KF + wn * 32 + nf * 8 + tc * 2;
            float2 bb = *(const float2*)&bias[col];
            float v0 = acc[mf][nf][0] + bb.x;
            float v1 = acc[mf][nf][1] + bb.y;
            float v2 = acc[mf][nf][2] + bb.x;
            float v3 = acc[mf][nf][3] + bb.y;
            v0 = v0 > 0.f ? v0 : 0.01f * v0;
            v1 = v1 > 0.f ? v1 : 0.01f * v1;
            v2 = v2 > 0.f ? v2 : 0.01f * v2;
            v3 = v3 > 0.f ? v3 : 0.01f * v3;
            float2 o01 = make_float2(v0, v1);
            float2 o23 = make_float2(v2, v3);
            *(float2*)&out[(size_t)row * OUTC + col] = o01;
            *(float2*)&out[(size_t)(row + 8) * OUTC + col] = o23;
        }
    }
}

// ---------------------------------------------------------------------------
extern "C" void kernel_launch(void* const* d_in, const int* in_sizes, int n_in,
                              void* d_out, int out_size) {
    const float* x    = (const float*)d_in[0];   // [2048,1,256,8,8]
    const float* cw   = (const float*)d_in[1];   // [4,128,84,8,8]
    const float* bias = (const float*)d_in[2];   // [4,128]
    float* out = (float*)d_out;                  // [2048,512]

    cudaFuncSetAttribute(k_gemm, cudaFuncAttributeMaxDynamicSharedMemorySize,
                         DSMEM);

    k_build_dwt<<<1, 64>>>();
    k_weff<<<SW_DIM * KF, 256>>>(cw);
    dim3 grid(SW_DIM, B_DIM / BM);
    k_gemm<<<grid, 256, DSMEM>>>(x, bias, out);
}

// round 4
// speedup vs baseline: 3.9578x; 1.6267x over previous
#include <cuda_runtime.h>
#include <cuda_fp16.h>
#include <cstdint>

// ---------------------------------------------------------------------------
// DWT_Features on GB300 (sm_103 PTX: mma.sync path):
//   1) k_weff: build 84x64 DWT matrix M in-block, fold into conv weights,
//      store W_eff as fp16  [s*128+n][k]
//   2) k_gemm: out = leaky(bias + x @ W_eff^T) via fp16 2-pass split
//      (Ah*B + Al*B), fp32 accumulate. M=2048, N=128 (x4 s), K=4096.
// ---------------------------------------------------------------------------

#define B_DIM    2048
#define SW_DIM   4
#define KF       128
#define DWT_LEN  84
#define KDIM     4096
#define OUTC     512
#define BK       128           // K per chunk (fp16)
#define NCHUNK   (KDIM / BK)   // 32
#define BM       64            // rows per CTA

// smem: padded rows 136 fp16 = 272 B (odd 16B-bank count -> ldsm conflict-free)
#define ROWB     272
#define OFF_AH   0
#define OFF_AL   17408         // 64*272
#define OFF_B    34816
#define STAGE    69632         // + 128*272
#define DSMEM    (2 * STAGE)   // 139264

__constant__ float c_dec_lo[8] = {
    -0.010597401784997278f,  0.032883011666982945f,  0.030841381835986965f,
    -0.18703481171888114f,  -0.02798376941698385f,   0.6308807679295904f,
     0.7148465705525415f,    0.23037781330885523f };
__constant__ float c_dec_hi[8] = {
    -0.23037781330885523f,   0.7148465705525415f,   -0.6308807679295904f,
    -0.02798376941698385f,   0.18703481171888114f,   0.030841381835986965f,
    -0.032883011666982945f, -0.010597401784997278f };

__device__ __align__(16) __half g_W[SW_DIM * KF * KDIM];   // [s*128+n][k]

// ---------------------------------------------------------------------------
__device__ __forceinline__ uint32_t smem_u32(const void* p) {
    uint32_t a;
    asm("{ .reg .u64 t; cvta.to.shared.u64 t, %1; cvt.u32.u64 %0, t; }"
        : "=r"(a) : "l"(p));
    return a;
}
__device__ __forceinline__ void cp16(uint32_t dst, const void* src) {
    asm volatile("cp.async.cg.shared.global [%0], [%1], 16;"
                 :: "r"(dst), "l"(src) : "memory");
}
__device__ __forceinline__ void ldsm4(uint32_t* r, uint32_t addr) {
    asm volatile("ldmatrix.sync.aligned.m8n8.x4.shared.b16 {%0,%1,%2,%3}, [%4];"
                 : "=r"(r[0]), "=r"(r[1]), "=r"(r[2]), "=r"(r[3]) : "r"(addr));
}
__device__ __forceinline__ void mma_f16(float* c, const uint32_t* a,
                                        const uint32_t* b) {
    asm volatile(
        "mma.sync.aligned.m16n8k16.row.col.f32.f16.f16.f32 "
        "{%0,%1,%2,%3}, {%4,%5,%6,%7}, {%8,%9}, {%0,%1,%2,%3};"
        : "+f"(c[0]), "+f"(c[1]), "+f"(c[2]), "+f"(c[3])
        : "r"(a[0]), "r"(a[1]), "r"(a[2]), "r"(a[3]), "r"(b[0]), "r"(b[1]));
}

// ---------------------------------------------------------------------------
// DWT level exactly matching reference _dwt_level (verified R1/R3).
// ---------------------------------------------------------------------------
__device__ void dwt_lvl(const float* x, int N, float* lo, int ls,
                        float* hi, int hs) {
    int outsize = (N + 7) >> 1;
    int p = 2 * (outsize - 1) - N + 8;
    int Nz = N + (p & 1);
    for (int j = 0; j < outsize; j++) {
        float sl = 0.f, sh = 0.f;
        #pragma unroll
        for (int i = 0; i < 8; i++) {
            int idx = 2 * j + i - 6;
            if (idx < 0) idx = -idx;
            if (idx > Nz - 1) idx = 2 * (Nz - 1) - idx;
            float v = (idx < N) ? x[idx] : 0.f;
            sl += v * c_dec_lo[7 - i];
            sh += v * c_dec_hi[7 - i];
        }
        lo[j * ls] = sl; hi[j * hs] = sh;
    }
}

// Level 1 on the identity basis vector (N=64, p even -> no zero append).
__device__ void dwt_lvl1_id(int tau, float* lo, int ls, float* hi, int hs) {
    for (int j = 0; j < 35; j++) {
        float sl = 0.f, sh = 0.f;
        #pragma unroll
        for (int i = 0; i < 8; i++) {
            int idx = 2 * j + i - 6;
            if (idx < 0) idx = -idx;
            if (idx > 63) idx = 126 - idx;
            if (idx == tau) { sl += c_dec_lo[7 - i]; sh += c_dec_hi[7 - i]; }
        }
        lo[j * ls] = sl; hi[j * hs] = sh;
    }
}

// ---------------------------------------------------------------------------
// k_weff: one block per (s,n). Build M (threads 0-63) while loading the
// weight slice (threads 64-255); then 4x4-register outer product over t;
// store fp16 W_eff.
// dyn smem: Ms[5376] | Ws[5376] | s1[64*36] | s2[64*24]  = 58368 B
// ---------------------------------------------------------------------------
#define WEFF_SMEM 58368

__global__ void __launch_bounds__(256)
k_weff(const float* __restrict__ cw) {
    extern __shared__ float wsm[];
    float* Ms = wsm;                    // [84*64], [t][tau]
    float* Ws = wsm + 5376;             // [84*64], [t][hw]
    float* s1 = wsm + 10752;            // [64][36]
    float* s2 = wsm + 13056;            // [64][24]

    const int tid = threadIdx.x;
    const int sn = blockIdx.x;          // s*128 + n
    const float* src = cw + (size_t)sn * (DWT_LEN * 64);

    if (tid < 64) {
        int tau = tid;
        dwt_lvl1_id(tau, s1 + tau * 36, 1, Ms + 14 * 64 + tau, 64);      // hi1
        dwt_lvl(s1 + tau * 36, 35, s2 + tau * 24, 1, Ms + 49 * 64 + tau, 64);
        dwt_lvl(s2 + tau * 24, 21, Ms + tau, 64, Ms + 70 * 64 + tau, 64);
    } else {
        for (int i = tid - 64; i < DWT_LEN * 64; i += 192) Ws[i] = src[i];
    }
    __syncthreads();

    const int tau0 = (tid >> 4) << 2;
    const int hw0 = (tid & 15) << 2;
    float acc[4][4];
    #pragma unroll
    for (int a = 0; a < 4; a++)
        #pragma unroll
        for (int b = 0; b < 4; b++) acc[a][b] = 0.f;

    for (int t = 0; t < DWT_LEN; t++) {
        float4 mv = *(const float4*)&Ms[t * 64 + tau0];
        float4 wv = *(const float4*)&Ws[t * 64 + hw0];
        const float m[4] = {mv.x, mv.y, mv.z, mv.w};
        const float w[4] = {wv.x, wv.y, wv.z, wv.w};
        #pragma unroll
        for (int a = 0; a < 4; a++)
            #pragma unroll
            for (int b = 0; b < 4; b++) acc[a][b] += m[a] * w[b];
    }

    __half* dst = g_W + (size_t)sn * KDIM;
    #pragma unroll
    for (int a = 0; a < 4; a++) {
        __half2 h01 = __float22half2_rn(make_float2(acc[a][0], acc[a][1]));
        __half2 h23 = __float22half2_rn(make_float2(acc[a][2], acc[a][3]));
        *(uint2*)&dst[(tau0 + a) * 64 + hw0] =
            make_uint2(*(uint32_t*)&h01, *(uint32_t*)&h23);
    }
}

// ---------------------------------------------------------------------------
// k_gemm: 512 threads = 16 warps (4m x 4n), warp tile 16x32, BK=128,
// double-buffered. A: LDG fp32 -> fp16 hi/lo split -> STS. B: cp.async fp16.
// ---------------------------------------------------------------------------
#define ISSUE_B(K0, STOFF) do {                                              \
    uint32_t _st = sbase + (STOFF) + OFF_B;                                  \
    _Pragma("unroll")                                                        \
    for (int _it = 0; _it < 4; _it++) {                                      \
        int _idx = tid + _it * 512;                                          \
        int _n = _idx >> 4, _seg = _idx & 15;                                \
        cp16(_st + _n * ROWB + _seg * 16,                                    \
             WB + (size_t)_n * KDIM + (K0) + _seg * 8);                      \
    }                                                                        \
    asm volatile("cp.async.commit_group;" ::: "memory");                     \
} while (0)

#define LDG_A(K0) do {                                                       \
    _Pragma("unroll")                                                        \
    for (int _it = 0; _it < 4; _it++) {                                      \
        int _idx = tid + _it * 512;                                          \
        int _row = _idx >> 5, _seg = _idx & 31;                              \
        areg[_it] = *(const float4*)(Abase +                                 \
            (size_t)_row * (SW_DIM * KDIM) + (K0) + _seg * 4);               \
    }                                                                        \
} while (0)

#define STS_A(STOFF) do {                                                    \
    char* _pb = sm + (STOFF);                                                \
    _Pragma("unroll")                                                        \
    for (int _it = 0; _it < 4; _it++) {                                      \
        int _idx = tid + _it * 512;                                          \
        int _row = _idx >> 5, _seg = _idx & 31;                              \
        float4 _v = areg[_it];                                               \
        __half2 _h01 = __float22half2_rn(make_float2(_v.x, _v.y));           \
        __half2 _h23 = __float22half2_rn(make_float2(_v.z, _v.w));           \
        float2 _f01 = __half22float2(_h01);                                  \
        float2 _f23 = __half22float2(_h23);                                  \
        __half2 _l01 = __float22half2_rn(                                    \
            make_float2(_v.x - _f01.x, _v.y - _f01.y));                      \
        __half2 _l23 = __float22half2_rn(                                    \
            make_float2(_v.z - _f23.x, _v.w - _f23.y));                      \
        uint32_t _o = _row * ROWB + _seg * 8;                                \
        *(uint2*)(_pb + OFF_AH + _o) =                                       \
            make_uint2(*(uint32_t*)&_h01, *(uint32_t*)&_h23);                \
        *(uint2*)(_pb + OFF_AL + _o) =                                       \
            make_uint2(*(uint32_t*)&_l01, *(uint32_t*)&_l23);                \
    }                                                                        \
} while (0)

__global__ void __launch_bounds__(512)
k_gemm(const float* __restrict__ x, const float* __restrict__ bias,
       float* __restrict__ out) {
    extern __shared__ char sm[];
    const int tid = threadIdx.x;
    const int wid = tid >> 5, lid = tid & 31;
    const int s = blockIdx.x;
    const int m0 = blockIdx.y * BM;
    const int wm = wid & 3, wn = wid >> 2;

    const uint32_t sbase = smem_u32(sm);
    const float* Abase = x + (size_t)m0 * (SW_DIM * KDIM) + (size_t)s * KDIM;
    const __half* WB = g_W + (size_t)s * KF * KDIM;

    const int q = lid >> 3, r = lid & 7;
    const uint32_t laneA = (wm * 16 + (q & 1) * 8 + r) * ROWB + (q >> 1) * 16;
    const uint32_t laneB = (wn * 32 + (q >> 1) * 8 + r) * ROWB + (q & 1) * 16;

    float acc[4][4];
    #pragma unroll
    for (int a = 0; a < 4; a++)
        #pragma unroll
        for (int b = 0; b < 4; b++) acc[a][b] = 0.f;

    float4 areg[4];

    ISSUE_B(0, 0);
    ISSUE_B(BK, STAGE);
    LDG_A(0);

    for (int i = 0; i < NCHUNK; i++) {
        const uint32_t stOff = (i & 1) ? STAGE : 0;
        STS_A(stOff);
        if (i < NCHUNK - 1)
            asm volatile("cp.async.wait_group 1;" ::: "memory");
        else
            asm volatile("cp.async.wait_group 0;" ::: "memory");
        __syncthreads();
        if (i + 1 < NCHUNK) LDG_A((i + 1) * BK);

        const uint32_t st = sbase + stOff;
        #pragma unroll
        for (int ks = 0; ks < 8; ks++) {
            const uint32_t ka = ks * 32;
            uint32_t Ah[4], Al[4], B0[4], B1[4];
            ldsm4(Ah, st + OFF_AH + laneA + ka);
            ldsm4(Al, st + OFF_AL + laneA + ka);
            ldsm4(B0, st + OFF_B + laneB + ka);
            ldsm4(B1, st + OFF_B + laneB + ka + 16 * ROWB);
            #pragma unroll
            for (int nf = 0; nf < 4; nf++)
                mma_f16(acc[nf], Ah, ((nf & 2) ? B1 : B0) + (nf & 1) * 2);
            #pragma unroll
            for (int nf = 0; nf < 4; nf++)
                mma_f16(acc[nf], Al, ((nf & 2) ? B1 : B0) + (nf & 1) * 2);
        }
        __syncthreads();
        if (i + 2 < NCHUNK) ISSUE_B((i + 2) * BK, stOff);
    }

    // epilogue: bias + leaky relu (slope 0.01)
    const int g = lid >> 2, tc = lid & 3;
    const int row = m0 + wm * 16 + g;
    #pragma unroll
    for (int nf = 0; nf < 4; nf++) {
        const int col = s * KF + wn * 32 + nf * 8 + tc * 2;
        float2 bb = *(const float2*)&bias[col];
        float v0 = acc[nf][0] + bb.x;
        float v1 = acc[nf][1] + bb.y;
        float v2 = acc[nf][2] + bb.x;
        float v3 = acc[nf][3] + bb.y;
        v0 = v0 > 0.f ? v0 : 0.01f * v0;
        v1 = v1 > 0.f ? v1 : 0.01f * v1;
        v2 = v2 > 0.f ? v2 : 0.01f * v2;
        v3 = v3 > 0.f ? v3 : 0.01f * v3;
        *(float2*)&out[(size_t)row * OUTC + col] = make_float2(v0, v1);
        *(float2*)&out[(size_t)(row + 8) * OUTC + col] = make_float2(v2, v3);
    }
}

// ---------------------------------------------------------------------------
extern "C" void kernel_launch(void* const* d_in, const int* in_sizes, int n_in,
                              void* d_out, int out_size) {
    const float* x    = (const float*)d_in[0];   // [2048,1,256,8,8]
    const float* cw   = (const float*)d_in[1];   // [4,128,84,8,8]
    const float* bias = (const float*)d_in[2];   // [4,128]
    float* out = (float*)d_out;                  // [2048,512]

    cudaFuncSetAttribute(k_weff, cudaFuncAttributeMaxDynamicSharedMemorySize,
                         WEFF_SMEM);
    cudaFuncSetAttribute(k_gemm, cudaFuncAttributeMaxDynamicSharedMemorySize,
                         DSMEM);

    k_weff<<<SW_DIM * KF, 256, WEFF_SMEM>>>(cw);
    dim3 grid(SW_DIM, B_DIM / BM);
    k_gemm<<<grid, 512, DSMEM>>>(x, bias, out);
}

// round 5
// speedup vs baseline: 4.2338x; 1.0698x over previous
#include <cuda_runtime.h>
#include <cuda_fp16.h>
#include <cstdint>

// ---------------------------------------------------------------------------
// DWT_Features on GB300 (sm_103 PTX: mma.sync path):
//   k_weff: build 84x64 DWT matrix M (parallel, analytic taps), fold into
//           conv weights with packed FFMA2 -> W_eff fp16 [s*128+n][k]
//   k_gemm: out = leaky(bias + x @ W_eff^T), fp16 2-pass split (Ah*B + Al*B),
//           fp32 accum. BM=32 BN=128 BK=64, 4 warps, 4 CTAs/SM.
// ---------------------------------------------------------------------------

#define B_DIM    2048
#define SW_DIM   4
#define KF       128
#define DWT_LEN  84
#define KDIM     4096
#define OUTC     512
#define BK       64
#define NCHUNK   (KDIM / BK)   // 64
#define BM       32

// smem rows padded: 64+8 halves = 144 B (conflict-free ldmatrix)
#define ROWB     144
#define OFF_AH   0
#define OFF_AL   4608          // 32*144
#define OFF_B    9216
#define STAGE    27648         // + 128*144
#define DSMEM    (2 * STAGE)   // 55296

__constant__ float c_dec_lo[8] = {
    -0.010597401784997278f,  0.032883011666982945f,  0.030841381835986965f,
    -0.18703481171888114f,  -0.02798376941698385f,   0.6308807679295904f,
     0.7148465705525415f,    0.23037781330885523f };
__constant__ float c_dec_hi[8] = {
    -0.23037781330885523f,   0.7148465705525415f,   -0.6308807679295904f,
    -0.02798376941698385f,   0.18703481171888114f,   0.030841381835986965f,
    -0.032883011666982945f, -0.010597401784997278f };

__device__ __align__(16) __half g_W[SW_DIM * KF * KDIM];   // [s*128+n][k]

// ---------------------------------------------------------------------------
__device__ __forceinline__ uint32_t smem_u32(const void* p) {
    uint32_t a;
    asm("{ .reg .u64 t; cvta.to.shared.u64 t, %1; cvt.u32.u64 %0, t; }"
        : "=r"(a) : "l"(p));
    return a;
}
__device__ __forceinline__ void cp16(uint32_t dst, const void* src) {
    asm volatile("cp.async.cg.shared.global [%0], [%1], 16;"
                 :: "r"(dst), "l"(src) : "memory");
}
__device__ __forceinline__ void ldsm4(uint32_t* r, uint32_t addr) {
    asm volatile("ldmatrix.sync.aligned.m8n8.x4.shared.b16 {%0,%1,%2,%3}, [%4];"
                 : "=r"(r[0]), "=r"(r[1]), "=r"(r[2]), "=r"(r[3]) : "r"(addr));
}
__device__ __forceinline__ void mma_f16(float* c, const uint32_t* a,
                                        const uint32_t* b) {
    asm volatile(
        "mma.sync.aligned.m16n8k16.row.col.f32.f16.f16.f32 "
        "{%0,%1,%2,%3}, {%4,%5,%6,%7}, {%8,%9}, {%0,%1,%2,%3};"
        : "+f"(c[0]), "+f"(c[1]), "+f"(c[2]), "+f"(c[3])
        : "r"(a[0]), "r"(a[1]), "r"(a[2]), "r"(a[3]), "r"(b[0]), "r"(b[1]));
}
__device__ __forceinline__ unsigned long long pack2(float x, float y) {
    unsigned long long r;
    asm("mov.b64 %0, {%1, %2};" : "=l"(r) : "f"(x), "f"(y));
    return r;
}
__device__ __forceinline__ void fma2(unsigned long long& d,
                                     unsigned long long a,
                                     unsigned long long b) {
    asm("fma.rn.f32x2 %0, %1, %2, %3;" : "=l"(d) : "l"(a), "l"(b), "l"(d));
}
__device__ __forceinline__ void unpack2(unsigned long long v, float& x, float& y) {
    asm("mov.b64 {%0, %1}, %2;" : "=f"(x), "=f"(y) : "l"(v));
}

// ---------------------------------------------------------------------------
// k_weff: one block per sn = s*128+n.
// Parallel M build: L1/H1 analytic (N=64, even pad, reflect at 0/63);
// L2/H2 from L1 (N=35, odd pad -> zero at idx 35, reflect at 35);
// L3/H3 from L2 (N=21, odd pad -> zero at idx 21, reflect at 21).
// Then fold: W_eff[tau*64+hw] = sum_t M[t][tau]*Ws[t][hw]  via FFMA2.
// smem floats: Ms[5376] Ws[5376] L1[2240] L2[1344] = 57344 B
// ---------------------------------------------------------------------------
#define WEFF_SMEM 57344

__global__ void __launch_bounds__(256)
k_weff(const float* __restrict__ cw) {
    extern __shared__ float wsm[];
    float* Ms = wsm;
    float* Ws = wsm + 5376;
    float* L1 = wsm + 10752;            // [35][64]
    float* L2 = wsm + 12992;            // [21][64]

    const int tid = threadIdx.x;
    const int sn = blockIdx.x;
    const float* src = cw + (size_t)sn * (DWT_LEN * 64);

    // async-load the weight slice while building M
    {
        uint32_t wsa = smem_u32(Ws);
        for (int i = tid; i < (DWT_LEN * 64) / 4; i += 256)
            cp16(wsa + i * 16, src + i * 4);
        asm volatile("cp.async.commit_group;" ::: "memory");
    }

    // level 1: analytic
    for (int e = tid; e < 35 * 64; e += 256) {
        int j = e >> 6, tau = e & 63;
        float sl = 0.f, sh = 0.f;
        #pragma unroll
        for (int i = 0; i < 8; i++) {
            int idx = 2 * j + i - 6;
            if (idx < 0) idx = -idx;
            if (idx > 63) idx = 126 - idx;
            if (idx == tau) { sl += c_dec_lo[7 - i]; sh += c_dec_hi[7 - i]; }
        }
        L1[j * 64 + tau] = sl;
        Ms[(14 + j) * 64 + tau] = sh;
    }
    __syncthreads();

    // level 2 from L1 (N=35, Nz=36)
    for (int e = tid; e < 21 * 64; e += 256) {
        int j = e >> 6, tau = e & 63;
        float sl = 0.f, sh = 0.f;
        #pragma unroll
        for (int i = 0; i < 8; i++) {
            int idx = 2 * j + i - 6;
            if (idx < 0) idx = -idx;
            if (idx > 35) idx = 70 - idx;
            if (idx < 35) {
                float v = L1[idx * 64 + tau];
                sl += v * c_dec_lo[7 - i];
                sh += v * c_dec_hi[7 - i];
            }
        }
        L2[j * 64 + tau] = sl;
        Ms[(49 + j) * 64 + tau] = sh;
    }
    __syncthreads();

    // level 3 from L2 (N=21, Nz=22)
    for (int e = tid; e < 14 * 64; e += 256) {
        int j = e >> 6, tau = e & 63;
        float sl = 0.f, sh = 0.f;
        #pragma unroll
        for (int i = 0; i < 8; i++) {
            int idx = 2 * j + i - 6;
            if (idx < 0) idx = -idx;
            if (idx > 21) idx = 42 - idx;
            if (idx < 21) {
                float v = L2[idx * 64 + tau];
                sl += v * c_dec_lo[7 - i];
                sh += v * c_dec_hi[7 - i];
            }
        }
        Ms[j * 64 + tau] = sl;
        Ms[(70 + j) * 64 + tau] = sh;
    }
    asm volatile("cp.async.wait_group 0;" ::: "memory");
    __syncthreads();

    // fold: 4x4 outer product per thread, packed f32x2
    const int tau0 = (tid >> 4) << 2;
    const int hw0 = (tid & 15) << 2;
    unsigned long long acc2[4][2];
    #pragma unroll
    for (int a = 0; a < 4; a++) { acc2[a][0] = 0ull; acc2[a][1] = 0ull; }

    #pragma unroll 4
    for (int t = 0; t < DWT_LEN; t++) {
        float4 mv = *(const float4*)&Ms[t * 64 + tau0];
        ulonglong2 wv = *(const ulonglong2*)&Ws[t * 64 + hw0];
        unsigned long long m0 = pack2(mv.x, mv.x);
        unsigned long long m1 = pack2(mv.y, mv.y);
        unsigned long long m2 = pack2(mv.z, mv.z);
        unsigned long long m3 = pack2(mv.w, mv.w);
        fma2(acc2[0][0], m0, wv.x); fma2(acc2[0][1], m0, wv.y);
        fma2(acc2[1][0], m1, wv.x); fma2(acc2[1][1], m1, wv.y);
        fma2(acc2[2][0], m2, wv.x); fma2(acc2[2][1], m2, wv.y);
        fma2(acc2[3][0], m3, wv.x); fma2(acc2[3][1], m3, wv.y);
    }

    __half* dst = g_W + (size_t)sn * KDIM;
    #pragma unroll
    for (int a = 0; a < 4; a++) {
        float v0, v1, v2, v3;
        unpack2(acc2[a][0], v0, v1);
        unpack2(acc2[a][1], v2, v3);
        __half2 h01 = __float22half2_rn(make_float2(v0, v1));
        __half2 h23 = __float22half2_rn(make_float2(v2, v3));
        *(uint2*)&dst[(tau0 + a) * 64 + hw0] =
            make_uint2(*(uint32_t*)&h01, *(uint32_t*)&h23);
    }
}

// ---------------------------------------------------------------------------
// k_gemm: 128 threads = 4 warps, each warp owns 32(m) x 32(n); BN=128 full.
// ---------------------------------------------------------------------------
#define ISSUE_B(K0, STOFF) do {                                              \
    uint32_t _st = sbase + (STOFF) + OFF_B;                                  \
    _Pragma("unroll")                                                        \
    for (int _it = 0; _it < 8; _it++) {                                      \
        int _idx = tid + _it * 128;                                          \
        int _n = _idx >> 3, _seg = _idx & 7;                                 \
        cp16(_st + _n * ROWB + _seg * 16,                                    \
             WB + (size_t)_n * KDIM + (K0) + _seg * 8);                      \
    }                                                                        \
    asm volatile("cp.async.commit_group;" ::: "memory");                     \
} while (0)

#define LDG_A(K0) do {                                                       \
    _Pragma("unroll")                                                        \
    for (int _it = 0; _it < 4; _it++) {                                      \
        int _idx = tid + _it * 128;                                          \
        int _row = _idx >> 4, _seg = _idx & 15;                              \
        areg[_it] = *(const float4*)(Abase +                                 \
            (size_t)_row * (SW_DIM * KDIM) + (K0) + _seg * 4);               \
    }                                                                        \
} while (0)

#define STS_A(STOFF) do {                                                    \
    char* _pb = sm + (STOFF);                                                \
    _Pragma("unroll")                                                        \
    for (int _it = 0; _it < 4; _it++) {                                      \
        int _idx = tid + _it * 128;                                          \
        int _row = _idx >> 4, _seg = _idx & 15;                              \
        float4 _v = areg[_it];                                               \
        __half2 _h01 = __float22half2_rn(make_float2(_v.x, _v.y));           \
        __half2 _h23 = __float22half2_rn(make_float2(_v.z, _v.w));           \
        float2 _f01 = __half22float2(_h01);                                  \
        float2 _f23 = __half22float2(_h23);                                  \
        __half2 _l01 = __float22half2_rn(                                    \
            make_float2(_v.x - _f01.x, _v.y - _f01.y));                      \
        __half2 _l23 = __float22half2_rn(                                    \
            make_float2(_v.z - _f23.x, _v.w - _f23.y));                      \
        uint32_t _o = _row * ROWB + _seg * 8;                                \
        *(uint2*)(_pb + OFF_AH + _o) =                                       \
            make_uint2(*(uint32_t*)&_h01, *(uint32_t*)&_h23);                \
        *(uint2*)(_pb + OFF_AL + _o) =                                       \
            make_uint2(*(uint32_t*)&_l01, *(uint32_t*)&_l23);                \
    }                                                                        \
} while (0)

__global__ void __launch_bounds__(128, 4)
k_gemm(const float* __restrict__ x, const float* __restrict__ bias,
       float* __restrict__ out) {
    extern __shared__ char sm[];
    const int tid = threadIdx.x;
    const int wid = tid >> 5, lid = tid & 31;
    const int s = blockIdx.x;
    const int m0 = blockIdx.y * BM;

    const uint32_t sbase = smem_u32(sm);
    const float* Abase = x + (size_t)m0 * (SW_DIM * KDIM) + (size_t)s * KDIM;
    const __half* WB = g_W + (size_t)s * KF * KDIM;

    const int q = lid >> 3, r = lid & 7;
    const uint32_t laneA = ((q & 1) * 8 + r) * ROWB + (q >> 1) * 16;
    const uint32_t laneB = (wid * 32 + (q >> 1) * 8 + r) * ROWB + (q & 1) * 16;

    float acc[2][4][4];
    #pragma unroll
    for (int a = 0; a < 2; a++)
        #pragma unroll
        for (int b = 0; b < 4; b++)
            #pragma unroll
            for (int c = 0; c < 4; c++) acc[a][b][c] = 0.f;

    float4 areg[4];

    ISSUE_B(0, 0);
    ISSUE_B(BK, STAGE);
    LDG_A(0);

    for (int i = 0; i < NCHUNK; i++) {
        const uint32_t stOff = (i & 1) ? STAGE : 0;
        STS_A(stOff);
        if (i + 1 < NCHUNK) LDG_A((i + 1) * BK);
        if (i < NCHUNK - 1)
            asm volatile("cp.async.wait_group 1;" ::: "memory");
        else
            asm volatile("cp.async.wait_group 0;" ::: "memory");
        __syncthreads();

        const uint32_t st = sbase + stOff;
        #pragma unroll
        for (int ks = 0; ks < 4; ks++) {
            const uint32_t ka = ks * 32;
            uint32_t Ah0[4], Ah1[4], Al0[4], Al1[4], B0[4], B1[4];
            ldsm4(Ah0, st + OFF_AH + laneA + ka);
            ldsm4(Ah1, st + OFF_AH + laneA + ka + 16 * ROWB);
            ldsm4(Al0, st + OFF_AL + laneA + ka);
            ldsm4(Al1, st + OFF_AL + laneA + ka + 16 * ROWB);
            ldsm4(B0, st + OFF_B + laneB + ka);
            ldsm4(B1, st + OFF_B + laneB + ka + 16 * ROWB);
            #pragma unroll
            for (int nf = 0; nf < 4; nf++) {
                const uint32_t* bb = ((nf & 2) ? B1 : B0) + (nf & 1) * 2;
                mma_f16(acc[0][nf], Ah0, bb);
                mma_f16(acc[1][nf], Ah1, bb);
                mma_f16(acc[0][nf], Al0, bb);
                mma_f16(acc[1][nf], Al1, bb);
            }
        }
        __syncthreads();
        if (i + 2 < NCHUNK) ISSUE_B((i + 2) * BK, stOff);
    }

    // epilogue: bias + leaky relu (slope 0.01)
    const int g = lid >> 2, tc = lid & 3;
    #pragma unroll
    for (int mf = 0; mf < 2; mf++) {
        const int row = m0 + mf * 16 + g;
        #pragma unroll
        for (int nf = 0; nf < 4; nf++) {
            const int col = s * KF + wid * 32 + nf * 8 + tc * 2;
            float2 bb = *(const float2*)&bias[col];
            float v0 = acc[mf][nf][0] + bb.x;
            float v1 = acc[mf][nf][1] + bb.y;
            float v2 = acc[mf][nf][2] + bb.x;
            float v3 = acc[mf][nf][3] + bb.y;
            v0 = v0 > 0.f ? v0 : 0.01f * v0;
            v1 = v1 > 0.f ? v1 : 0.01f * v1;
            v2 = v2 > 0.f ? v2 : 0.01f * v2;
            v3 = v3 > 0.f ? v3 : 0.01f * v3;
            *(float2*)&out[(size_t)row * OUTC + col] = make_float2(v0, v1);
            *(float2*)&out[(size_t)(row + 8) * OUTC + col] = make_float2(v2, v3);
        }
    }
}

// ---------------------------------------------------------------------------
extern "C" void kernel_launch(void* const* d_in, const int* in_sizes, int n_in,
                              void* d_out, int out_size) {
    const float* x    = (const float*)d_in[0];   // [2048,1,256,8,8]
    const float* cw   = (const float*)d_in[1];   // [4,128,84,8,8]
    const float* bias = (const float*)d_in[2];   // [4,128]
    float* out = (float*)d_out;                  // [2048,512]

    cudaFuncSetAttribute(k_weff, cudaFuncAttributeMaxDynamicSharedMemorySize,
                         WEFF_SMEM);
    cudaFuncSetAttribute(k_gemm, cudaFuncAttributeMaxDynamicSharedMemorySize,
                         DSMEM);

    k_weff<<<SW_DIM * KF, 256, WEFF_SMEM>>>(cw);
    dim3 grid(SW_DIM, B_DIM / BM);
    k_gemm<<<grid, 128, DSMEM>>>(x, bias, out);
}

// round 6
// speedup vs baseline: 4.5267x; 1.0692x over previous
#include <cuda_runtime.h>
#include <cuda_fp16.h>
#include <cstdint>

// ---------------------------------------------------------------------------
// DWT_Features on GB300 (sm_103 PTX: mma.sync path):
//   k_weff: build 84x64 DWT matrix M (parallel, analytic taps), fold into
//           conv weights with packed FFMA2 -> W_eff fp16 [s*128+n][k]
//   k_gemm: split-K=2 partial GEMM, fp16 2-pass split (Ah*B + Al*B), fp32 acc
//   k_fin:  out = leaky(p0 + p1 + bias)
// ---------------------------------------------------------------------------

#define B_DIM    2048
#define SW_DIM   4
#define KF       128
#define DWT_LEN  84
#define KDIM     4096
#define KSPLIT   2
#define KHALF    (KDIM / KSPLIT)   // 2048
#define OUTC     512
#define BK       64
#define NCHUNK   (KHALF / BK)      // 32
#define BM       32

// smem rows padded: 64+8 halves = 144 B (conflict-free ldmatrix)
#define ROWB     144
#define OFF_AH   0
#define OFF_AL   4608          // 32*144
#define OFF_B    9216
#define STAGE    27648         // + 128*144
#define DSMEM    (2 * STAGE)   // 55296

__constant__ float c_dec_lo[8] = {
    -0.010597401784997278f,  0.032883011666982945f,  0.030841381835986965f,
    -0.18703481171888114f,  -0.02798376941698385f,   0.6308807679295904f,
     0.7148465705525415f,    0.23037781330885523f };
__constant__ float c_dec_hi[8] = {
    -0.23037781330885523f,   0.7148465705525415f,   -0.6308807679295904f,
    -0.02798376941698385f,   0.18703481171888114f,   0.030841381835986965f,
    -0.032883011666982945f, -0.010597401784997278f };

__device__ __align__(16) __half g_W[SW_DIM * KF * KDIM];          // [s*128+n][k]
__device__ __align__(16) float g_part[KSPLIT][B_DIM][OUTC];       // 8.4 MB

// ---------------------------------------------------------------------------
__device__ __forceinline__ uint32_t smem_u32(const void* p) {
    uint32_t a;
    asm("{ .reg .u64 t; cvta.to.shared.u64 t, %1; cvt.u32.u64 %0, t; }"
        : "=r"(a) : "l"(p));
    return a;
}
__device__ __forceinline__ void cp16(uint32_t dst, const void* src) {
    asm volatile("cp.async.cg.shared.global [%0], [%1], 16;"
                 :: "r"(dst), "l"(src) : "memory");
}
__device__ __forceinline__ void ldsm4(uint32_t* r, uint32_t addr) {
    asm volatile("ldmatrix.sync.aligned.m8n8.x4.shared.b16 {%0,%1,%2,%3}, [%4];"
                 : "=r"(r[0]), "=r"(r[1]), "=r"(r[2]), "=r"(r[3]) : "r"(addr));
}
__device__ __forceinline__ void mma_f16(float* c, const uint32_t* a,
                                        const uint32_t* b) {
    asm volatile(
        "mma.sync.aligned.m16n8k16.row.col.f32.f16.f16.f32 "
        "{%0,%1,%2,%3}, {%4,%5,%6,%7}, {%8,%9}, {%0,%1,%2,%3};"
        : "+f"(c[0]), "+f"(c[1]), "+f"(c[2]), "+f"(c[3])
        : "r"(a[0]), "r"(a[1]), "r"(a[2]), "r"(a[3]), "r"(b[0]), "r"(b[1]));
}
__device__ __forceinline__ unsigned long long pack2(float x, float y) {
    unsigned long long r;
    asm("mov.b64 %0, {%1, %2};" : "=l"(r) : "f"(x), "f"(y));
    return r;
}
__device__ __forceinline__ void fma2(unsigned long long& d,
                                     unsigned long long a,
                                     unsigned long long b) {
    asm("fma.rn.f32x2 %0, %1, %2, %3;" : "=l"(d) : "l"(a), "l"(b), "l"(d));
}
__device__ __forceinline__ void unpack2(unsigned long long v, float& x, float& y) {
    asm("mov.b64 {%0, %1}, %2;" : "=f"(x), "=f"(y) : "l"(v));
}

// ---------------------------------------------------------------------------
// k_weff: one block per sn = s*128+n (verified R5).
// ---------------------------------------------------------------------------
#define WEFF_SMEM 57344

__global__ void __launch_bounds__(256)
k_weff(const float* __restrict__ cw) {
    extern __shared__ float wsm[];
    float* Ms = wsm;
    float* Ws = wsm + 5376;
    float* L1 = wsm + 10752;            // [35][64]
    float* L2 = wsm + 12992;            // [21][64]

    const int tid = threadIdx.x;
    const int sn = blockIdx.x;
    const float* src = cw + (size_t)sn * (DWT_LEN * 64);

    {
        uint32_t wsa = smem_u32(Ws);
        for (int i = tid; i < (DWT_LEN * 64) / 4; i += 256)
            cp16(wsa + i * 16, src + i * 4);
        asm volatile("cp.async.commit_group;" ::: "memory");
    }

    for (int e = tid; e < 35 * 64; e += 256) {
        int j = e >> 6, tau = e & 63;
        float sl = 0.f, sh = 0.f;
        #pragma unroll
        for (int i = 0; i < 8; i++) {
            int idx = 2 * j + i - 6;
            if (idx < 0) idx = -idx;
            if (idx > 63) idx = 126 - idx;
            if (idx == tau) { sl += c_dec_lo[7 - i]; sh += c_dec_hi[7 - i]; }
        }
        L1[j * 64 + tau] = sl;
        Ms[(14 + j) * 64 + tau] = sh;
    }
    __syncthreads();

    for (int e = tid; e < 21 * 64; e += 256) {
        int j = e >> 6, tau = e & 63;
        float sl = 0.f, sh = 0.f;
        #pragma unroll
        for (int i = 0; i < 8; i++) {
            int idx = 2 * j + i - 6;
            if (idx < 0) idx = -idx;
            if (idx > 35) idx = 70 - idx;
            if (idx < 35) {
                float v = L1[idx * 64 + tau];
                sl += v * c_dec_lo[7 - i];
                sh += v * c_dec_hi[7 - i];
            }
        }
        L2[j * 64 + tau] = sl;
        Ms[(49 + j) * 64 + tau] = sh;
    }
    __syncthreads();

    for (int e = tid; e < 14 * 64; e += 256) {
        int j = e >> 6, tau = e & 63;
        float sl = 0.f, sh = 0.f;
        #pragma unroll
        for (int i = 0; i < 8; i++) {
            int idx = 2 * j + i - 6;
            if (idx < 0) idx = -idx;
            if (idx > 21) idx = 42 - idx;
            if (idx < 21) {
                float v = L2[idx * 64 + tau];
                sl += v * c_dec_lo[7 - i];
                sh += v * c_dec_hi[7 - i];
            }
        }
        Ms[j * 64 + tau] = sl;
        Ms[(70 + j) * 64 + tau] = sh;
    }
    asm volatile("cp.async.wait_group 0;" ::: "memory");
    __syncthreads();

    const int tau0 = (tid >> 4) << 2;
    const int hw0 = (tid & 15) << 2;
    unsigned long long acc2[4][2];
    #pragma unroll
    for (int a = 0; a < 4; a++) { acc2[a][0] = 0ull; acc2[a][1] = 0ull; }

    #pragma unroll 4
    for (int t = 0; t < DWT_LEN; t++) {
        float4 mv = *(const float4*)&Ms[t * 64 + tau0];
        ulonglong2 wv = *(const ulonglong2*)&Ws[t * 64 + hw0];
        unsigned long long m0 = pack2(mv.x, mv.x);
        unsigned long long m1 = pack2(mv.y, mv.y);
        unsigned long long m2 = pack2(mv.z, mv.z);
        unsigned long long m3 = pack2(mv.w, mv.w);
        fma2(acc2[0][0], m0, wv.x); fma2(acc2[0][1], m0, wv.y);
        fma2(acc2[1][0], m1, wv.x); fma2(acc2[1][1], m1, wv.y);
        fma2(acc2[2][0], m2, wv.x); fma2(acc2[2][1], m2, wv.y);
        fma2(acc2[3][0], m3, wv.x); fma2(acc2[3][1], m3, wv.y);
    }

    __half* dst = g_W + (size_t)sn * KDIM;
    #pragma unroll
    for (int a = 0; a < 4; a++) {
        float v0, v1, v2, v3;
        unpack2(acc2[a][0], v0, v1);
        unpack2(acc2[a][1], v2, v3);
        __half2 h01 = __float22half2_rn(make_float2(v0, v1));
        __half2 h23 = __float22half2_rn(make_float2(v2, v3));
        *(uint2*)&dst[(tau0 + a) * 64 + hw0] =
            make_uint2(*(uint32_t*)&h01, *(uint32_t*)&h23);
    }
}

// ---------------------------------------------------------------------------
// k_gemm: split-K partial. grid.x = s*2+ks (8), grid.y = m-tile (64).
// 128 threads = 4 warps, warp tile 32(m) x 32(n).
// ---------------------------------------------------------------------------
#define ISSUE_B(K0, STOFF) do {                                              \
    uint32_t _st = sbase + (STOFF) + OFF_B;                                  \
    _Pragma("unroll")                                                        \
    for (int _it = 0; _it < 8; _it++) {                                      \
        int _idx = tid + _it * 128;                                          \
        int _n = _idx >> 3, _seg = _idx & 7;                                 \
        cp16(_st + _n * ROWB + _seg * 16,                                    \
             WB + (size_t)_n * KDIM + (K0) + _seg * 8);                      \
    }                                                                        \
    asm volatile("cp.async.commit_group;" ::: "memory");                     \
} while (0)

#define LDG_A(K0) do {                                                       \
    _Pragma("unroll")                                                        \
    for (int _it = 0; _it < 4; _it++) {                                      \
        int _idx = tid + _it * 128;                                          \
        int _row = _idx >> 4, _seg = _idx & 15;                              \
        areg[_it] = *(const float4*)(Abase +                                 \
            (size_t)_row * (SW_DIM * KDIM) + (K0) + _seg * 4);               \
    }                                                                        \
} while (0)

#define STS_A(STOFF) do {                                                    \
    char* _pb = sm + (STOFF);                                                \
    _Pragma("unroll")                                                        \
    for (int _it = 0; _it < 4; _it++) {                                      \
        int _idx = tid + _it * 128;                                          \
        int _row = _idx >> 4, _seg = _idx & 15;                              \
        float4 _v = areg[_it];                                               \
        __half2 _h01 = __float22half2_rn(make_float2(_v.x, _v.y));           \
        __half2 _h23 = __float22half2_rn(make_float2(_v.z, _v.w));           \
        float2 _f01 = __half22float2(_h01);                                  \
        float2 _f23 = __half22float2(_h23);                                  \
        __half2 _l01 = __float22half2_rn(                                    \
            make_float2(_v.x - _f01.x, _v.y - _f01.y));                      \
        __half2 _l23 = __float22half2_rn(                                    \
            make_float2(_v.z - _f23.x, _v.w - _f23.y));                      \
        uint32_t _o = _row * ROWB + _seg * 8;                                \
        *(uint2*)(_pb + OFF_AH + _o) =                                       \
            make_uint2(*(uint32_t*)&_h01, *(uint32_t*)&_h23);                \
        *(uint2*)(_pb + OFF_AL + _o) =                                       \
            make_uint2(*(uint32_t*)&_l01, *(uint32_t*)&_l23);                \
    }                                                                        \
} while (0)

__global__ void __launch_bounds__(128, 4)
k_gemm(const float* __restrict__ x) {
    extern __shared__ char sm[];
    const int tid = threadIdx.x;
    const int wid = tid >> 5, lid = tid & 31;
    const int s = blockIdx.x >> 1;
    const int ks = blockIdx.x & 1;
    const int m0 = blockIdx.y * BM;
    const int kbase = ks * KHALF;

    const uint32_t sbase = smem_u32(sm);
    const float* Abase = x + (size_t)m0 * (SW_DIM * KDIM) + (size_t)s * KDIM
                         + kbase;
    const __half* WB = g_W + (size_t)s * KF * KDIM + kbase;

    const int q = lid >> 3, r = lid & 7;
    const uint32_t laneA = ((q & 1) * 8 + r) * ROWB + (q >> 1) * 16;
    const uint32_t laneB = (wid * 32 + (q >> 1) * 8 + r) * ROWB + (q & 1) * 16;

    float acc[2][4][4];
    #pragma unroll
    for (int a = 0; a < 2; a++)
        #pragma unroll
        for (int b = 0; b < 4; b++)
            #pragma unroll
            for (int c = 0; c < 4; c++) acc[a][b][c] = 0.f;

    float4 areg[4];

    ISSUE_B(0, 0);
    ISSUE_B(BK, STAGE);
    LDG_A(0);

    for (int i = 0; i < NCHUNK; i++) {
        const uint32_t stOff = (i & 1) ? STAGE : 0;
        STS_A(stOff);
        if (i + 1 < NCHUNK) LDG_A((i + 1) * BK);
        if (i < NCHUNK - 1)
            asm volatile("cp.async.wait_group 1;" ::: "memory");
        else
            asm volatile("cp.async.wait_group 0;" ::: "memory");
        __syncthreads();

        const uint32_t st = sbase + stOff;
        #pragma unroll
        for (int ks4 = 0; ks4 < 4; ks4++) {
            const uint32_t ka = ks4 * 32;
            uint32_t Ah0[4], Ah1[4], Al0[4], Al1[4], B0[4], B1[4];
            ldsm4(Ah0, st + OFF_AH + laneA + ka);
            ldsm4(Ah1, st + OFF_AH + laneA + ka + 16 * ROWB);
            ldsm4(Al0, st + OFF_AL + laneA + ka);
            ldsm4(Al1, st + OFF_AL + laneA + ka + 16 * ROWB);
            ldsm4(B0, st + OFF_B + laneB + ka);
            ldsm4(B1, st + OFF_B + laneB + ka + 16 * ROWB);
            // hi pass: 8 independent MMAs, then lo pass (dep distance 8)
            #pragma unroll
            for (int nf = 0; nf < 4; nf++) {
                const uint32_t* bb = ((nf & 2) ? B1 : B0) + (nf & 1) * 2;
                mma_f16(acc[0][nf], Ah0, bb);
                mma_f16(acc[1][nf], Ah1, bb);
            }
            #pragma unroll
            for (int nf = 0; nf < 4; nf++) {
                const uint32_t* bb = ((nf & 2) ? B1 : B0) + (nf & 1) * 2;
                mma_f16(acc[0][nf], Al0, bb);
                mma_f16(acc[1][nf], Al1, bb);
            }
        }
        __syncthreads();
        if (i + 2 < NCHUNK) ISSUE_B((i + 2) * BK, stOff);
    }

    // write fp32 partial (no bias/relu)
    const int g = lid >> 2, tc = lid & 3;
    float* pbase = &g_part[ks][0][0];
    #pragma unroll
    for (int mf = 0; mf < 2; mf++) {
        const int row = m0 + mf * 16 + g;
        #pragma unroll
        for (int nf = 0; nf < 4; nf++) {
            const int col = s * KF + wid * 32 + nf * 8 + tc * 2;
            *(float2*)&pbase[(size_t)row * OUTC + col] =
                make_float2(acc[mf][nf][0], acc[mf][nf][1]);
            *(float2*)&pbase[(size_t)(row + 8) * OUTC + col] =
                make_float2(acc[mf][nf][2], acc[mf][nf][3]);
        }
    }
}

// ---------------------------------------------------------------------------
// finalize: out = leaky(p0 + p1 + bias)
// ---------------------------------------------------------------------------
__global__ void __launch_bounds__(256)
k_fin(const float* __restrict__ bias, float* __restrict__ out) {
    int i = blockIdx.x * 256 + threadIdx.x;        // float4 index
    float4 a = *(const float4*)(&g_part[0][0][0] + (size_t)i * 4);
    float4 b = *(const float4*)(&g_part[1][0][0] + (size_t)i * 4);
    int col = (i * 4) & (OUTC - 1);
    float4 bb = *(const float4*)&bias[col];
    float v0 = a.x + b.x + bb.x;
    float v1 = a.y + b.y + bb.y;
    float v2 = a.z + b.z + bb.z;
    float v3 = a.w + b.w + bb.w;
    v0 = v0 > 0.f ? v0 : 0.01f * v0;
    v1 = v1 > 0.f ? v1 : 0.01f * v1;
    v2 = v2 > 0.f ? v2 : 0.01f * v2;
    v3 = v3 > 0.f ? v3 : 0.01f * v3;
    *(float4*)&out[(size_t)i * 4] = make_float4(v0, v1, v2, v3);
}

// ---------------------------------------------------------------------------
extern "C" void kernel_launch(void* const* d_in, const int* in_sizes, int n_in,
                              void* d_out, int out_size) {
    const float* x    = (const float*)d_in[0];   // [2048,1,256,8,8]
    const float* cw   = (const float*)d_in[1];   // [4,128,84,8,8]
    const float* bias = (const float*)d_in[2];   // [4,128]
    float* out = (float*)d_out;                  // [2048,512]

    cudaFuncSetAttribute(k_weff, cudaFuncAttributeMaxDynamicSharedMemorySize,
                         WEFF_SMEM);
    cudaFuncSetAttribute(k_gemm, cudaFuncAttributeMaxDynamicSharedMemorySize,
                         DSMEM);

    k_weff<<<SW_DIM * KF, 256, WEFF_SMEM>>>(cw);
    dim3 grid(SW_DIM * KSPLIT, B_DIM / BM);
    k_gemm<<<grid, 128, DSMEM>>>(x);
    k_fin<<<(B_DIM * OUTC / 4) / 256, 256>>>(bias, out);
}

// round 7
// speedup vs baseline: 5.6512x; 1.2484x over previous
#include <cuda_runtime.h>
#include <cuda_fp16.h>
#include <cstdint>

// ---------------------------------------------------------------------------
// DWT_Features on GB300 (sm_103 PTX: mma.sync path):
//   k_mbuild: build 84x64 DWT matrix M once -> g_M
//   k_weff:   fold M into conv weights (FFMA2) -> W_eff fp16 [s*128+n][k]
//   k_gemm:   split-K=2 partial GEMM, SINGLE-pass fp16 (A hi only), fp32 acc
//   k_fin:    out = leaky(p0 + p1 + bias)
// ---------------------------------------------------------------------------

#define B_DIM    2048
#define SW_DIM   4
#define KF       128
#define DWT_LEN  84
#define KDIM     4096
#define KSPLIT   2
#define KHALF    (KDIM / KSPLIT)   // 2048
#define OUTC     512
#define BK       64
#define NCHUNK   (KHALF / BK)      // 32
#define BM       32

// smem rows padded: 64+8 halves = 144 B (conflict-free ldmatrix)
#define ROWB     144
#define OFF_AH   0
#define OFF_B    4608          // 32*144
#define STAGE    23040         // + 128*144
#define DSMEM    (2 * STAGE)   // 46080

__constant__ float c_dec_lo[8] = {
    -0.010597401784997278f,  0.032883011666982945f,  0.030841381835986965f,
    -0.18703481171888114f,  -0.02798376941698385f,   0.6308807679295904f,
     0.7148465705525415f,    0.23037781330885523f };
__constant__ float c_dec_hi[8] = {
    -0.23037781330885523f,   0.7148465705525415f,   -0.6308807679295904f,
    -0.02798376941698385f,   0.18703481171888114f,   0.030841381835986965f,
    -0.032883011666982945f, -0.010597401784997278f };

__device__ float g_M[DWT_LEN * 64];                               // 84 x 64
__device__ __align__(16) __half g_W[SW_DIM * KF * KDIM];          // [s*128+n][k]
__device__ __align__(16) float g_part[KSPLIT][B_DIM][OUTC];       // 8.4 MB

// ---------------------------------------------------------------------------
__device__ __forceinline__ uint32_t smem_u32(const void* p) {
    uint32_t a;
    asm("{ .reg .u64 t; cvta.to.shared.u64 t, %1; cvt.u32.u64 %0, t; }"
        : "=r"(a) : "l"(p));
    return a;
}
__device__ __forceinline__ void cp16(uint32_t dst, const void* src) {
    asm volatile("cp.async.cg.shared.global [%0], [%1], 16;"
                 :: "r"(dst), "l"(src) : "memory");
}
__device__ __forceinline__ void ldsm4(uint32_t* r, uint32_t addr) {
    asm volatile("ldmatrix.sync.aligned.m8n8.x4.shared.b16 {%0,%1,%2,%3}, [%4];"
                 : "=r"(r[0]), "=r"(r[1]), "=r"(r[2]), "=r"(r[3]) : "r"(addr));
}
__device__ __forceinline__ void mma_f16(float* c, const uint32_t* a,
                                        const uint32_t* b) {
    asm volatile(
        "mma.sync.aligned.m16n8k16.row.col.f32.f16.f16.f32 "
        "{%0,%1,%2,%3}, {%4,%5,%6,%7}, {%8,%9}, {%0,%1,%2,%3};"
        : "+f"(c[0]), "+f"(c[1]), "+f"(c[2]), "+f"(c[3])
        : "r"(a[0]), "r"(a[1]), "r"(a[2]), "r"(a[3]), "r"(b[0]), "r"(b[1]));
}
__device__ __forceinline__ unsigned long long pack2(float x, float y) {
    unsigned long long r;
    asm("mov.b64 %0, {%1, %2};" : "=l"(r) : "f"(x), "f"(y));
    return r;
}
__device__ __forceinline__ void fma2(unsigned long long& d,
                                     unsigned long long a,
                                     unsigned long long b) {
    asm("fma.rn.f32x2 %0, %1, %2, %3;" : "=l"(d) : "l"(a), "l"(b), "l"(d));
}
__device__ __forceinline__ void unpack2(unsigned long long v, float& x, float& y) {
    asm("mov.b64 {%0, %1}, %2;" : "=f"(x), "=f"(y) : "l"(v));
}

// ---------------------------------------------------------------------------
// k_mbuild: build 84x64 DWT matrix once (one block, 256 threads).
// ---------------------------------------------------------------------------
__global__ void __launch_bounds__(256)
k_mbuild() {
    __shared__ float L1[35 * 64], L2[21 * 64];
    const int tid = threadIdx.x;

    for (int e = tid; e < 35 * 64; e += 256) {
        int j = e >> 6, tau = e & 63;
        float sl = 0.f, sh = 0.f;
        #pragma unroll
        for (int i = 0; i < 8; i++) {
            int idx = 2 * j + i - 6;
            if (idx < 0) idx = -idx;
            if (idx > 63) idx = 126 - idx;
            if (idx == tau) { sl += c_dec_lo[7 - i]; sh += c_dec_hi[7 - i]; }
        }
        L1[j * 64 + tau] = sl;
        g_M[(14 + j) * 64 + tau] = sh;
    }
    __syncthreads();

    for (int e = tid; e < 21 * 64; e += 256) {
        int j = e >> 6, tau = e & 63;
        float sl = 0.f, sh = 0.f;
        #pragma unroll
        for (int i = 0; i < 8; i++) {
            int idx = 2 * j + i - 6;
            if (idx < 0) idx = -idx;
            if (idx > 35) idx = 70 - idx;
            if (idx < 35) {
                float v = L1[idx * 64 + tau];
                sl += v * c_dec_lo[7 - i];
                sh += v * c_dec_hi[7 - i];
            }
        }
        L2[j * 64 + tau] = sl;
        g_M[(49 + j) * 64 + tau] = sh;
    }
    __syncthreads();

    for (int e = tid; e < 14 * 64; e += 256) {
        int j = e >> 6, tau = e & 63;
        float sl = 0.f, sh = 0.f;
        #pragma unroll
        for (int i = 0; i < 8; i++) {
            int idx = 2 * j + i - 6;
            if (idx < 0) idx = -idx;
            if (idx > 21) idx = 42 - idx;
            if (idx < 21) {
                float v = L2[idx * 64 + tau];
                sl += v * c_dec_lo[7 - i];
                sh += v * c_dec_hi[7 - i];
            }
        }
        g_M[j * 64 + tau] = sl;
        g_M[(70 + j) * 64 + tau] = sh;
    }
}

// ---------------------------------------------------------------------------
// k_weff: pure fold. one block per sn = s*128+n.
// W_eff[tau*64+hw] = sum_t M[t][tau] * Ws[t][hw], 4x4 per thread, FFMA2.
// smem: Ms[5376] + Ws[5376] floats = 43008 B
// ---------------------------------------------------------------------------
#define WEFF_SMEM 43008

__global__ void __launch_bounds__(256)
k_weff(const float* __restrict__ cw) {
    extern __shared__ float wsm[];
    float* Ms = wsm;
    float* Ws = wsm + 5376;

    const int tid = threadIdx.x;
    const int sn = blockIdx.x;
    const float* src = cw + (size_t)sn * (DWT_LEN * 64);

    {
        uint32_t msa = smem_u32(Ms);
        uint32_t wsa = smem_u32(Ws);
        for (int i = tid; i < (DWT_LEN * 64) / 4; i += 256) {
            cp16(msa + i * 16, g_M + i * 4);
            cp16(wsa + i * 16, src + i * 4);
        }
        asm volatile("cp.async.commit_group;" ::: "memory");
        asm volatile("cp.async.wait_group 0;" ::: "memory");
    }
    __syncthreads();

    const int tau0 = (tid >> 4) << 2;
    const int hw0 = (tid & 15) << 2;
    unsigned long long acc2[4][2];
    #pragma unroll
    for (int a = 0; a < 4; a++) { acc2[a][0] = 0ull; acc2[a][1] = 0ull; }

    #pragma unroll 4
    for (int t = 0; t < DWT_LEN; t++) {
        float4 mv = *(const float4*)&Ms[t * 64 + tau0];
        ulonglong2 wv = *(const ulonglong2*)&Ws[t * 64 + hw0];
        unsigned long long m0 = pack2(mv.x, mv.x);
        unsigned long long m1 = pack2(mv.y, mv.y);
        unsigned long long m2 = pack2(mv.z, mv.z);
        unsigned long long m3 = pack2(mv.w, mv.w);
        fma2(acc2[0][0], m0, wv.x); fma2(acc2[0][1], m0, wv.y);
        fma2(acc2[1][0], m1, wv.x); fma2(acc2[1][1], m1, wv.y);
        fma2(acc2[2][0], m2, wv.x); fma2(acc2[2][1], m2, wv.y);
        fma2(acc2[3][0], m3, wv.x); fma2(acc2[3][1], m3, wv.y);
    }

    __half* dst = g_W + (size_t)sn * KDIM;
    #pragma unroll
    for (int a = 0; a < 4; a++) {
        float v0, v1, v2, v3;
        unpack2(acc2[a][0], v0, v1);
        unpack2(acc2[a][1], v2, v3);
        __half2 h01 = __float22half2_rn(make_float2(v0, v1));
        __half2 h23 = __float22half2_rn(make_float2(v2, v3));
        *(uint2*)&dst[(tau0 + a) * 64 + hw0] =
            make_uint2(*(uint32_t*)&h01, *(uint32_t*)&h23);
    }
}

// ---------------------------------------------------------------------------
// k_gemm: split-K partial, SINGLE-pass fp16. grid.x = s*2+ks, grid.y = m-tile.
// 128 threads = 4 warps, warp tile 32(m) x 32(n).
// ---------------------------------------------------------------------------
#define ISSUE_B(K0, STOFF) do {                                              \
    uint32_t _st = sbase + (STOFF) + OFF_B;                                  \
    _Pragma("unroll")                                                        \
    for (int _it = 0; _it < 8; _it++) {                                      \
        int _idx = tid + _it * 128;                                          \
        int _n = _idx >> 3, _seg = _idx & 7;                                 \
        cp16(_st + _n * ROWB + _seg * 16,                                    \
             WB + (size_t)_n * KDIM + (K0) + _seg * 8);                      \
    }                                                                        \
    asm volatile("cp.async.commit_group;" ::: "memory");                     \
} while (0)

#define LDG_A(K0) do {                                                       \
    _Pragma("unroll")                                                        \
    for (int _it = 0; _it < 4; _it++) {                                      \
        int _idx = tid + _it * 128;                                          \
        int _row = _idx >> 4, _seg = _idx & 15;                              \
        areg[_it] = *(const float4*)(Abase +                                 \
            (size_t)_row * (SW_DIM * KDIM) + (K0) + _seg * 4);               \
    }                                                                        \
} while (0)

#define STS_A(STOFF) do {                                                    \
    char* _pb = sm + (STOFF);                                                \
    _Pragma("unroll")                                                        \
    for (int _it = 0; _it < 4; _it++) {                                      \
        int _idx = tid + _it * 128;                                          \
        int _row = _idx >> 4, _seg = _idx & 15;                              \
        float4 _v = areg[_it];                                               \
        __half2 _h01 = __float22half2_rn(make_float2(_v.x, _v.y));           \
        __half2 _h23 = __float22half2_rn(make_float2(_v.z, _v.w));           \
        *(uint2*)(_pb + OFF_AH + _row * ROWB + _seg * 8) =                   \
            make_uint2(*(uint32_t*)&_h01, *(uint32_t*)&_h23);                \
    }                                                                        \
} while (0)

__global__ void __launch_bounds__(128, 4)
k_gemm(const float* __restrict__ x) {
    extern __shared__ char sm[];
    const int tid = threadIdx.x;
    const int wid = tid >> 5, lid = tid & 31;
    const int s = blockIdx.x >> 1;
    const int ks = blockIdx.x & 1;
    const int m0 = blockIdx.y * BM;
    const int kbase = ks * KHALF;

    const uint32_t sbase = smem_u32(sm);
    const float* Abase = x + (size_t)m0 * (SW_DIM * KDIM) + (size_t)s * KDIM
                         + kbase;
    const __half* WB = g_W + (size_t)s * KF * KDIM + kbase;

    const int q = lid >> 3, r = lid & 7;
    const uint32_t laneA = ((q & 1) * 8 + r) * ROWB + (q >> 1) * 16;
    const uint32_t laneB = (wid * 32 + (q >> 1) * 8 + r) * ROWB + (q & 1) * 16;

    float acc[2][4][4];
    #pragma unroll
    for (int a = 0; a < 2; a++)
        #pragma unroll
        for (int b = 0; b < 4; b++)
            #pragma unroll
            for (int c = 0; c < 4; c++) acc[a][b][c] = 0.f;

    float4 areg[4];

    ISSUE_B(0, 0);
    ISSUE_B(BK, STAGE);
    LDG_A(0);

    for (int i = 0; i < NCHUNK; i++) {
        const uint32_t stOff = (i & 1) ? STAGE : 0;
        STS_A(stOff);
        if (i + 1 < NCHUNK) LDG_A((i + 1) * BK);
        if (i < NCHUNK - 1)
            asm volatile("cp.async.wait_group 1;" ::: "memory");
        else
            asm volatile("cp.async.wait_group 0;" ::: "memory");
        __syncthreads();

        const uint32_t st = sbase + stOff;
        #pragma unroll
        for (int ks4 = 0; ks4 < 4; ks4++) {
            const uint32_t ka = ks4 * 32;
            uint32_t Ah0[4], Ah1[4], B0[4], B1[4];
            ldsm4(Ah0, st + OFF_AH + laneA + ka);
            ldsm4(Ah1, st + OFF_AH + laneA + ka + 16 * ROWB);
            ldsm4(B0, st + OFF_B + laneB + ka);
            ldsm4(B1, st + OFF_B + laneB + ka + 16 * ROWB);
            #pragma unroll
            for (int nf = 0; nf < 4; nf++) {
                const uint32_t* bb = ((nf & 2) ? B1 : B0) + (nf & 1) * 2;
                mma_f16(acc[0][nf], Ah0, bb);
                mma_f16(acc[1][nf], Ah1, bb);
            }
        }
        __syncthreads();
        if (i + 2 < NCHUNK) ISSUE_B((i + 2) * BK, stOff);
    }

    // write fp32 partial (no bias/relu)
    const int g = lid >> 2, tc = lid & 3;
    float* pbase = &g_part[ks][0][0];
    #pragma unroll
    for (int mf = 0; mf < 2; mf++) {
        const int row = m0 + mf * 16 + g;
        #pragma unroll
        for (int nf = 0; nf < 4; nf++) {
            const int col = s * KF + wid * 32 + nf * 8 + tc * 2;
            *(float2*)&pbase[(size_t)row * OUTC + col] =
                make_float2(acc[mf][nf][0], acc[mf][nf][1]);
            *(float2*)&pbase[(size_t)(row + 8) * OUTC + col] =
                make_float2(acc[mf][nf][2], acc[mf][nf][3]);
        }
    }
}

// ---------------------------------------------------------------------------
// finalize: out = leaky(p0 + p1 + bias)
// ---------------------------------------------------------------------------
__global__ void __launch_bounds__(256)
k_fin(const float* __restrict__ bias, float* __restrict__ out) {
    int i = blockIdx.x * 256 + threadIdx.x;        // float4 index
    float4 a = *(const float4*)(&g_part[0][0][0] + (size_t)i * 4);
    float4 b = *(const float4*)(&g_part[1][0][0] + (size_t)i * 4);
    int col = (i * 4) & (OUTC - 1);
    float4 bb = *(const float4*)&bias[col];
    float v0 = a.x + b.x + bb.x;
    float v1 = a.y + b.y + bb.y;
    float v2 = a.z + b.z + bb.z;
    float v3 = a.w + b.w + bb.w;
    v0 = v0 > 0.f ? v0 : 0.01f * v0;
    v1 = v1 > 0.f ? v1 : 0.01f * v1;
    v2 = v2 > 0.f ? v2 : 0.01f * v2;
    v3 = v3 > 0.f ? v3 : 0.01f * v3;
    *(float4*)&out[(size_t)i * 4] = make_float4(v0, v1, v2, v3);
}

// ---------------------------------------------------------------------------
extern "C" void kernel_launch(void* const* d_in, const int* in_sizes, int n_in,
                              void* d_out, int out_size) {
    const float* x    = (const float*)d_in[0];   // [2048,1,256,8,8]
    const float* cw   = (const float*)d_in[1];   // [4,128,84,8,8]
    const float* bias = (const float*)d_in[2];   // [4,128]
    float* out = (float*)d_out;                  // [2048,512]

    cudaFuncSetAttribute(k_weff, cudaFuncAttributeMaxDynamicSharedMemorySize,
                         WEFF_SMEM);
    cudaFuncSetAttribute(k_gemm, cudaFuncAttributeMaxDynamicSharedMemorySize,
                         DSMEM);

    k_mbuild<<<1, 256>>>();
    k_weff<<<SW_DIM * KF, 256, WEFF_SMEM>>>(cw);
    dim3 grid(SW_DIM * KSPLIT, B_DIM / BM);
    k_gemm<<<grid, 128, DSMEM>>>(x);
    k_fin<<<(B_DIM * OUTC / 4) / 256, 256>>>(bias, out);
}

// round 9
// speedup vs baseline: 6.0293x; 1.0669x over previous
#include <cuda_runtime.h>
#include <cuda_fp16.h>
#include <cstdint>

// ---------------------------------------------------------------------------
// DWT_Features on GB300 (sm_103 PTX: mma.sync path):
//   k_mbuild: build 84x64 DWT matrix M once -> g_M
//   k_weff:   fold M into conv weights (FFMA2) -> W_eff fp16 [s*128+n][k]
//   k_gemm:   split-K=4 partial GEMM, single-pass fp16, BM=128 BN=128 BK=32
//   k_fin:    out = leaky(p0+p1+p2+p3 + bias)
// ---------------------------------------------------------------------------

#define B_DIM    2048
#define SW_DIM   4
#define KF       128
#define DWT_LEN  84
#define KDIM     4096
#define KSPLIT   4
#define KQ       (KDIM / KSPLIT)   // 1024
#define OUTC     512
#define BK       32
#define NCHUNK   (KQ / BK)         // 32
#define BM       128

// smem rows: 32 halves + 8 pad = 80 B (stride 5 x16B, coprime 8 -> ldsm clean)
#define ROWB     80
#define OFF_B    10240          // 128*80
#define STAGE    20480          // + 128*80
#define DSMEM    (2 * STAGE)    // 40960

__constant__ float c_dec_lo[8] = {
    -0.010597401784997278f,  0.032883011666982945f,  0.030841381835986965f,
    -0.18703481171888114f,  -0.02798376941698385f,   0.6308807679295904f,
     0.7148465705525415f,    0.23037781330885523f };
__constant__ float c_dec_hi[8] = {
    -0.23037781330885523f,   0.7148465705525415f,   -0.6308807679295904f,
    -0.02798376941698385f,   0.18703481171888114f,   0.030841381835986965f,
    -0.032883011666982945f, -0.010597401784997278f };

__device__ float g_M[DWT_LEN * 64];                               // 84 x 64
__device__ __align__(16) __half g_W[SW_DIM * KF * KDIM];          // [s*128+n][k]
__device__ __align__(16) float g_part[KSPLIT][B_DIM][OUTC];       // 16.8 MB

// ---------------------------------------------------------------------------
__device__ __forceinline__ uint32_t smem_u32(const void* p) {
    uint32_t a;
    asm("{ .reg .u64 t; cvta.to.shared.u64 t, %1; cvt.u32.u64 %0, t; }"
        : "=r"(a) : "l"(p));
    return a;
}
__device__ __forceinline__ void cp16(uint32_t dst, const void* src) {
    asm volatile("cp.async.cg.shared.global [%0], [%1], 16;"
                 :: "r"(dst), "l"(src) : "memory");
}
__device__ __forceinline__ void ldsm4(uint32_t* r, uint32_t addr) {
    asm volatile("ldmatrix.sync.aligned.m8n8.x4.shared.b16 {%0,%1,%2,%3}, [%4];"
                 : "=r"(r[0]), "=r"(r[1]), "=r"(r[2]), "=r"(r[3]) : "r"(addr));
}
__device__ __forceinline__ void mma_f16(float* c, const uint32_t* a,
                                        const uint32_t* b) {
    asm volatile(
        "mma.sync.aligned.m16n8k16.row.col.f32.f16.f16.f32 "
        "{%0,%1,%2,%3}, {%4,%5,%6,%7}, {%8,%9}, {%0,%1,%2,%3};"
        : "+f"(c[0]), "+f"(c[1]), "+f"(c[2]), "+f"(c[3])
        : "r"(a[0]), "r"(a[1]), "r"(a[2]), "r"(a[3]), "r"(b[0]), "r"(b[1]));
}
__device__ __forceinline__ unsigned long long pack2(float x, float y) {
    unsigned long long r;
    asm("mov.b64 %0, {%1, %2};" : "=l"(r) : "f"(x), "f"(y));
    return r;
}
__device__ __forceinline__ void fma2(unsigned long long& d,
                                     unsigned long long a,
                                     unsigned long long b) {
    asm("fma.rn.f32x2 %0, %1, %2, %3;" : "=l"(d) : "l"(a), "l"(b), "l"(d));
}
__device__ __forceinline__ void unpack2(unsigned long long v, float& x, float& y) {
    asm("mov.b64 {%0, %1}, %2;" : "=f"(x), "=f"(y) : "l"(v));
}

// ---------------------------------------------------------------------------
// k_mbuild: build 84x64 DWT matrix once (verified R7).
// ---------------------------------------------------------------------------
__global__ void __launch_bounds__(256)
k_mbuild() {
    __shared__ float L1[35 * 64], L2[21 * 64];
    const int tid = threadIdx.x;

    for (int e = tid; e < 35 * 64; e += 256) {
        int j = e >> 6, tau = e & 63;
        float sl = 0.f, sh = 0.f;
        #pragma unroll
        for (int i = 0; i < 8; i++) {
            int idx = 2 * j + i - 6;
            if (idx < 0) idx = -idx;
            if (idx > 63) idx = 126 - idx;
            if (idx == tau) { sl += c_dec_lo[7 - i]; sh += c_dec_hi[7 - i]; }
        }
        L1[j * 64 + tau] = sl;
        g_M[(14 + j) * 64 + tau] = sh;
    }
    __syncthreads();

    for (int e = tid; e < 21 * 64; e += 256) {
        int j = e >> 6, tau = e & 63;
        float sl = 0.f, sh = 0.f;
        #pragma unroll
        for (int i = 0; i < 8; i++) {
            int idx = 2 * j + i - 6;
            if (idx < 0) idx = -idx;
            if (idx > 35) idx = 70 - idx;
            if (idx < 35) {
                float v = L1[idx * 64 + tau];
                sl += v * c_dec_lo[7 - i];
                sh += v * c_dec_hi[7 - i];
            }
        }
        L2[j * 64 + tau] = sl;
        g_M[(49 + j) * 64 + tau] = sh;
    }
    __syncthreads();

    for (int e = tid; e < 14 * 64; e += 256) {
        int j = e >> 6, tau = e & 63;
        float sl = 0.f, sh = 0.f;
        #pragma unroll
        for (int i = 0; i < 8; i++) {
            int idx = 2 * j + i - 6;
            if (idx < 0) idx = -idx;
            if (idx > 21) idx = 42 - idx;
            if (idx < 21) {
                float v = L2[idx * 64 + tau];
                sl += v * c_dec_lo[7 - i];
                sh += v * c_dec_hi[7 - i];
            }
        }
        g_M[j * 64 + tau] = sl;
        g_M[(70 + j) * 64 + tau] = sh;
    }
}

// ---------------------------------------------------------------------------
// k_weff: pure fold (verified R7). one block per sn = s*128+n.
// ---------------------------------------------------------------------------
#define WEFF_SMEM 43008

__global__ void __launch_bounds__(256)
k_weff(const float* __restrict__ cw) {
    extern __shared__ float wsm[];
    float* Ms = wsm;
    float* Ws = wsm + 5376;

    const int tid = threadIdx.x;
    const int sn = blockIdx.x;
    const float* src = cw + (size_t)sn * (DWT_LEN * 64);

    {
        uint32_t msa = smem_u32(Ms);
        uint32_t wsa = smem_u32(Ws);
        for (int i = tid; i < (DWT_LEN * 64) / 4; i += 256) {
            cp16(msa + i * 16, g_M + i * 4);
            cp16(wsa + i * 16, src + i * 4);
        }
        asm volatile("cp.async.commit_group;" ::: "memory");
        asm volatile("cp.async.wait_group 0;" ::: "memory");
    }
    __syncthreads();

    const int tau0 = (tid >> 4) << 2;
    const int hw0 = (tid & 15) << 2;
    unsigned long long acc2[4][2];
    #pragma unroll
    for (int a = 0; a < 4; a++) { acc2[a][0] = 0ull; acc2[a][1] = 0ull; }

    #pragma unroll 4
    for (int t = 0; t < DWT_LEN; t++) {
        float4 mv = *(const float4*)&Ms[t * 64 + tau0];
        ulonglong2 wv = *(const ulonglong2*)&Ws[t * 64 + hw0];
        unsigned long long m0 = pack2(mv.x, mv.x);
        unsigned long long m1 = pack2(mv.y, mv.y);
        unsigned long long m2 = pack2(mv.z, mv.z);
        unsigned long long m3 = pack2(mv.w, mv.w);
        fma2(acc2[0][0], m0, wv.x); fma2(acc2[0][1], m0, wv.y);
        fma2(acc2[1][0], m1, wv.x); fma2(acc2[1][1], m1, wv.y);
        fma2(acc2[2][0], m2, wv.x); fma2(acc2[2][1], m2, wv.y);
        fma2(acc2[3][0], m3, wv.x); fma2(acc2[3][1], m3, wv.y);
    }

    __half* dst = g_W + (size_t)sn * KDIM;
    #pragma unroll
    for (int a = 0; a < 4; a++) {
        float v0, v1, v2, v3;
        unpack2(acc2[a][0], v0, v1);
        unpack2(acc2[a][1], v2, v3);
        __half2 h01 = __float22half2_rn(make_float2(v0, v1));
        __half2 h23 = __float22half2_rn(make_float2(v2, v3));
        *(uint2*)&dst[(tau0 + a) * 64 + hw0] =
            make_uint2(*(uint32_t*)&h01, *(uint32_t*)&h23);
    }
}

// ---------------------------------------------------------------------------
// k_gemm: BM=128, BN=128, BK=32, split-K=4. 256 threads = 8 warps (2m x 4n),
// warp tile 64x32. grid.x = s*4+ks (16), grid.y = m-tile (16).
// B fill: 128 rows x 64 B = 512 cp16 slots -> _n = idx>>2, _seg = idx&3.
// ---------------------------------------------------------------------------
#define ISSUE_B(K0, STOFF) do {                                              \
    uint32_t _st = sbase + (STOFF) + OFF_B;                                  \
    _Pragma("unroll")                                                        \
    for (int _it = 0; _it < 2; _it++) {                                      \
        int _idx = tid + _it * 256;                                          \
        int _n = _idx >> 2, _seg = _idx & 3;                                 \
        cp16(_st + _n * ROWB + _seg * 16,                                    \
             WB + (size_t)_n * KDIM + (K0) + _seg * 8);                      \
    }                                                                        \
    asm volatile("cp.async.commit_group;" ::: "memory");                     \
} while (0)

#define LDG_A(K0) do {                                                       \
    _Pragma("unroll")                                                        \
    for (int _it = 0; _it < 4; _it++) {                                      \
        int _idx = tid + _it * 256;                                          \
        int _row = _idx >> 3, _seg = _idx & 7;                               \
        areg[_it] = *(const float4*)(Abase +                                 \
            (size_t)_row * (SW_DIM * KDIM) + (K0) + _seg * 4);               \
    }                                                                        \
} while (0)

#define STS_A(STOFF) do {                                                    \
    char* _pb = sm + (STOFF);                                                \
    _Pragma("unroll")                                                        \
    for (int _it = 0; _it < 4; _it++) {                                      \
        int _idx = tid + _it * 256;                                          \
        int _row = _idx >> 3, _seg = _idx & 7;                               \
        float4 _v = areg[_it];                                               \
        __half2 _h01 = __float22half2_rn(make_float2(_v.x, _v.y));           \
        __half2 _h23 = __float22half2_rn(make_float2(_v.z, _v.w));           \
        *(uint2*)(_pb + _row * ROWB + _seg * 8) =                            \
            make_uint2(*(uint32_t*)&_h01, *(uint32_t*)&_h23);                \
    }                                                                        \
} while (0)

__global__ void __launch_bounds__(256, 2)
k_gemm(const float* __restrict__ x) {
    extern __shared__ char sm[];
    const int tid = threadIdx.x;
    const int wid = tid >> 5, lid = tid & 31;
    const int s = blockIdx.x >> 2;
    const int ks = blockIdx.x & 3;
    const int m0 = blockIdx.y * BM;
    const int kbase = ks * KQ;
    const int wm = wid & 1, wn = wid >> 1;

    const uint32_t sbase = smem_u32(sm);
    const float* Abase = x + (size_t)m0 * (SW_DIM * KDIM) + (size_t)s * KDIM
                         + kbase;
    const __half* WB = g_W + (size_t)s * KF * KDIM + kbase;

    const int q = lid >> 3, r = lid & 7;
    const uint32_t laneA = (wm * 64 + (q & 1) * 8 + r) * ROWB + (q >> 1) * 16;
    const uint32_t laneB = (wn * 32 + (q >> 1) * 8 + r) * ROWB + (q & 1) * 16;

    float acc[4][4][4];
    #pragma unroll
    for (int a = 0; a < 4; a++)
        #pragma unroll
        for (int b = 0; b < 4; b++)
            #pragma unroll
            for (int c = 0; c < 4; c++) acc[a][b][c] = 0.f;

    float4 areg[4];

    ISSUE_B(0, 0);
    ISSUE_B(BK, STAGE);
    LDG_A(0);

    for (int i = 0; i < NCHUNK; i++) {
        const uint32_t stOff = (i & 1) ? STAGE : 0;
        STS_A(stOff);
        if (i + 1 < NCHUNK) LDG_A((i + 1) * BK);
        if (i < NCHUNK - 1)
            asm volatile("cp.async.wait_group 1;" ::: "memory");
        else
            asm volatile("cp.async.wait_group 0;" ::: "memory");
        __syncthreads();

        const uint32_t st = sbase + stOff;
        #pragma unroll
        for (int kk = 0; kk < 2; kk++) {
            const uint32_t ka = kk * 32;        // bytes: k16 slice
            uint32_t Af[4][4], B0[4], B1[4];
            ldsm4(B0, st + OFF_B + laneB + ka);
            ldsm4(B1, st + OFF_B + laneB + ka + 16 * ROWB);
            #pragma unroll
            for (int mf = 0; mf < 4; mf++)
                ldsm4(Af[mf], st + laneA + mf * (16 * ROWB) + ka);
            #pragma unroll
            for (int mf = 0; mf < 4; mf++) {
                #pragma unroll
                for (int nf = 0; nf < 4; nf++) {
                    const uint32_t* bb = ((nf & 2) ? B1 : B0) + (nf & 1) * 2;
                    mma_f16(acc[mf][nf], Af[mf], bb);
                }
            }
        }
        __syncthreads();
        if (i + 2 < NCHUNK) ISSUE_B((i + 2) * BK, stOff);
    }

    // write fp32 partial (no bias/relu)
    const int g = lid >> 2, tc = lid & 3;
    float* pbase = &g_part[ks][0][0];
    #pragma unroll
    for (int mf = 0; mf < 4; mf++) {
        const int row = m0 + wm * 64 + mf * 16 + g;
        #pragma unroll
        for (int nf = 0; nf < 4; nf++) {
            const int col = s * KF + wn * 32 + nf * 8 + tc * 2;
            *(float2*)&pbase[(size_t)row * OUTC + col] =
                make_float2(acc[mf][nf][0], acc[mf][nf][1]);
            *(float2*)&pbase[(size_t)(row + 8) * OUTC + col] =
                make_float2(acc[mf][nf][2], acc[mf][nf][3]);
        }
    }
}

// ---------------------------------------------------------------------------
// finalize: out = leaky(p0+p1+p2+p3 + bias)
// ---------------------------------------------------------------------------
__global__ void __launch_bounds__(256)
k_fin(const float* __restrict__ bias, float* __restrict__ out) {
    int i = blockIdx.x * 256 + threadIdx.x;        // float4 index
    float4 a = *(const float4*)(&g_part[0][0][0] + (size_t)i * 4);
    float4 b = *(const float4*)(&g_part[1][0][0] + (size_t)i * 4);
    float4 c = *(const float4*)(&g_part[2][0][0] + (size_t)i * 4);
    float4 d = *(const float4*)(&g_part[3][0][0] + (size_t)i * 4);
    int col = (i * 4) & (OUTC - 1);
    float4 bb = *(const float4*)&bias[col];
    float v0 = (a.x + b.x) + (c.x + d.x) + bb.x;
    float v1 = (a.y + b.y) + (c.y + d.y) + bb.y;
    float v2 = (a.z + b.z) + (c.z + d.z) + bb.z;
    float v3 = (a.w + b.w) + (c.w + d.w) + bb.w;
    v0 = v0 > 0.f ? v0 : 0.01f * v0;
    v1 = v1 > 0.f ? v1 : 0.01f * v1;
    v2 = v2 > 0.f ? v2 : 0.01f * v2;
    v3 = v3 > 0.f ? v3 : 0.01f * v3;
    *(float4*)&out[(size_t)i * 4] = make_float4(v0, v1, v2, v3);
}

// ---------------------------------------------------------------------------
extern "C" void kernel_launch(void* const* d_in, const int* in_sizes, int n_in,
                              void* d_out, int out_size) {
    const float* x    = (const float*)d_in[0];   // [2048,1,256,8,8]
    const float* cw   = (const float*)d_in[1];   // [4,128,84,8,8]
    const float* bias = (const float*)d_in[2];   // [4,128]
    float* out = (float*)d_out;                  // [2048,512]

    cudaFuncSetAttribute(k_weff, cudaFuncAttributeMaxDynamicSharedMemorySize,
                         WEFF_SMEM);
    cudaFuncSetAttribute(k_gemm, cudaFuncAttributeMaxDynamicSharedMemorySize,
                         DSMEM);

    k_mbuild<<<1, 256>>>();
    k_weff<<<SW_DIM * KF, 256, WEFF_SMEM>>>(cw);
    dim3 grid(SW_DIM * KSPLIT, B_DIM / BM);
    k_gemm<<<grid, 256, DSMEM>>>(x);
    k_fin<<<(B_DIM * OUTC / 4) / 256, 256>>>(bias, out);
}

// round 10
// speedup vs baseline: 6.0952x; 1.0109x over previous
#include <cuda_runtime.h>
#include <cuda_fp16.h>
#include <cstdint>

// ---------------------------------------------------------------------------
// DWT_Features on GB300 (sm_103 PTX: mma.sync path):
//   k_mbuild: build 84x64 DWT matrix M once -> g_M
//   k_weff:   fold M into conv weights (FFMA2) -> W_eff fp16 [s*128+n][k]
//   k_gemm:   split-K=4 partial GEMM, single-pass fp16, BM=128 BN=128 BK=32,
//             one __syncthreads per chunk (A 2-buf, B 3-buf cp.async)
//   k_fin:    out = leaky(p0+p1+p2+p3 + bias)
// ---------------------------------------------------------------------------

#define B_DIM    2048
#define SW_DIM   4
#define KF       128
#define DWT_LEN  84
#define KDIM     4096
#define KSPLIT   4
#define KQ       (KDIM / KSPLIT)   // 1024
#define OUTC     512
#define BK       32
#define NCHUNK   (KQ / BK)         // 32
#define BM       128

// smem rows: 32 halves + 8 pad = 80 B (stride 5 x16B, coprime 8 -> ldsm clean)
#define ROWB     80
#define TILEB    10240             // 128*80
#define AOFF(j)  ((j) * TILEB)                 // j in {0,1}
#define BOFF(j)  (2 * TILEB + (j) * TILEB)     // j in {0,1,2}
#define DSMEM    (5 * TILEB)       // 51200

__constant__ float c_dec_lo[8] = {
    -0.010597401784997278f,  0.032883011666982945f,  0.030841381835986965f,
    -0.18703481171888114f,  -0.02798376941698385f,   0.6308807679295904f,
     0.7148465705525415f,    0.23037781330885523f };
__constant__ float c_dec_hi[8] = {
    -0.23037781330885523f,   0.7148465705525415f,   -0.6308807679295904f,
    -0.02798376941698385f,   0.18703481171888114f,   0.030841381835986965f,
    -0.032883011666982945f, -0.010597401784997278f };

__device__ float g_M[DWT_LEN * 64];                               // 84 x 64
__device__ __align__(16) __half g_W[SW_DIM * KF * KDIM];          // [s*128+n][k]
__device__ __align__(16) float g_part[KSPLIT][B_DIM][OUTC];       // 16.8 MB

// ---------------------------------------------------------------------------
__device__ __forceinline__ uint32_t smem_u32(const void* p) {
    uint32_t a;
    asm("{ .reg .u64 t; cvta.to.shared.u64 t, %1; cvt.u32.u64 %0, t; }"
        : "=r"(a) : "l"(p));
    return a;
}
__device__ __forceinline__ void cp16(uint32_t dst, const void* src) {
    asm volatile("cp.async.cg.shared.global [%0], [%1], 16;"
                 :: "r"(dst), "l"(src) : "memory");
}
__device__ __forceinline__ void ldsm4(uint32_t* r, uint32_t addr) {
    asm volatile("ldmatrix.sync.aligned.m8n8.x4.shared.b16 {%0,%1,%2,%3}, [%4];"
                 : "=r"(r[0]), "=r"(r[1]), "=r"(r[2]), "=r"(r[3]) : "r"(addr));
}
__device__ __forceinline__ void mma_f16(float* c, const uint32_t* a,
                                        const uint32_t* b) {
    asm volatile(
        "mma.sync.aligned.m16n8k16.row.col.f32.f16.f16.f32 "
        "{%0,%1,%2,%3}, {%4,%5,%6,%7}, {%8,%9}, {%0,%1,%2,%3};"
        : "+f"(c[0]), "+f"(c[1]), "+f"(c[2]), "+f"(c[3])
        : "r"(a[0]), "r"(a[1]), "r"(a[2]), "r"(a[3]), "r"(b[0]), "r"(b[1]));
}
__device__ __forceinline__ unsigned long long pack2(float x, float y) {
    unsigned long long r;
    asm("mov.b64 %0, {%1, %2};" : "=l"(r) : "f"(x), "f"(y));
    return r;
}
__device__ __forceinline__ void fma2(unsigned long long& d,
                                     unsigned long long a,
                                     unsigned long long b) {
    asm("fma.rn.f32x2 %0, %1, %2, %3;" : "=l"(d) : "l"(a), "l"(b), "l"(d));
}
__device__ __forceinline__ void unpack2(unsigned long long v, float& x, float& y) {
    asm("mov.b64 {%0, %1}, %2;" : "=f"(x), "=f"(y) : "l"(v));
}

// ---------------------------------------------------------------------------
// k_mbuild: build 84x64 DWT matrix once (verified).
// ---------------------------------------------------------------------------
__global__ void __launch_bounds__(256)
k_mbuild() {
    __shared__ float L1[35 * 64], L2[21 * 64];
    const int tid = threadIdx.x;

    for (int e = tid; e < 35 * 64; e += 256) {
        int j = e >> 6, tau = e & 63;
        float sl = 0.f, sh = 0.f;
        #pragma unroll
        for (int i = 0; i < 8; i++) {
            int idx = 2 * j + i - 6;
            if (idx < 0) idx = -idx;
            if (idx > 63) idx = 126 - idx;
            if (idx == tau) { sl += c_dec_lo[7 - i]; sh += c_dec_hi[7 - i]; }
        }
        L1[j * 64 + tau] = sl;
        g_M[(14 + j) * 64 + tau] = sh;
    }
    __syncthreads();

    for (int e = tid; e < 21 * 64; e += 256) {
        int j = e >> 6, tau = e & 63;
        float sl = 0.f, sh = 0.f;
        #pragma unroll
        for (int i = 0; i < 8; i++) {
            int idx = 2 * j + i - 6;
            if (idx < 0) idx = -idx;
            if (idx > 35) idx = 70 - idx;
            if (idx < 35) {
                float v = L1[idx * 64 + tau];
                sl += v * c_dec_lo[7 - i];
                sh += v * c_dec_hi[7 - i];
            }
        }
        L2[j * 64 + tau] = sl;
        g_M[(49 + j) * 64 + tau] = sh;
    }
    __syncthreads();

    for (int e = tid; e < 14 * 64; e += 256) {
        int j = e >> 6, tau = e & 63;
        float sl = 0.f, sh = 0.f;
        #pragma unroll
        for (int i = 0; i < 8; i++) {
            int idx = 2 * j + i - 6;
            if (idx < 0) idx = -idx;
            if (idx > 21) idx = 42 - idx;
            if (idx < 21) {
                float v = L2[idx * 64 + tau];
                sl += v * c_dec_lo[7 - i];
                sh += v * c_dec_hi[7 - i];
            }
        }
        g_M[j * 64 + tau] = sl;
        g_M[(70 + j) * 64 + tau] = sh;
    }
}

// ---------------------------------------------------------------------------
// k_weff: pure fold (verified). one block per sn = s*128+n.
// ---------------------------------------------------------------------------
#define WEFF_SMEM 43008

__global__ void __launch_bounds__(256)
k_weff(const float* __restrict__ cw) {
    extern __shared__ float wsm[];
    float* Ms = wsm;
    float* Ws = wsm + 5376;

    const int tid = threadIdx.x;
    const int sn = blockIdx.x;
    const float* src = cw + (size_t)sn * (DWT_LEN * 64);

    {
        uint32_t msa = smem_u32(Ms);
        uint32_t wsa = smem_u32(Ws);
        for (int i = tid; i < (DWT_LEN * 64) / 4; i += 256) {
            cp16(msa + i * 16, g_M + i * 4);
            cp16(wsa + i * 16, src + i * 4);
        }
        asm volatile("cp.async.commit_group;" ::: "memory");
        asm volatile("cp.async.wait_group 0;" ::: "memory");
    }
    __syncthreads();

    const int tau0 = (tid >> 4) << 2;
    const int hw0 = (tid & 15) << 2;
    unsigned long long acc2[4][2];
    #pragma unroll
    for (int a = 0; a < 4; a++) { acc2[a][0] = 0ull; acc2[a][1] = 0ull; }

    #pragma unroll 4
    for (int t = 0; t < DWT_LEN; t++) {
        float4 mv = *(const float4*)&Ms[t * 64 + tau0];
        ulonglong2 wv = *(const ulonglong2*)&Ws[t * 64 + hw0];
        unsigned long long m0 = pack2(mv.x, mv.x);
        unsigned long long m1 = pack2(mv.y, mv.y);
        unsigned long long m2 = pack2(mv.z, mv.z);
        unsigned long long m3 = pack2(mv.w, mv.w);
        fma2(acc2[0][0], m0, wv.x); fma2(acc2[0][1], m0, wv.y);
        fma2(acc2[1][0], m1, wv.x); fma2(acc2[1][1], m1, wv.y);
        fma2(acc2[2][0], m2, wv.x); fma2(acc2[2][1], m2, wv.y);
        fma2(acc2[3][0], m3, wv.x); fma2(acc2[3][1], m3, wv.y);
    }

    __half* dst = g_W + (size_t)sn * KDIM;
    #pragma unroll
    for (int a = 0; a < 4; a++) {
        float v0, v1, v2, v3;
        unpack2(acc2[a][0], v0, v1);
        unpack2(acc2[a][1], v2, v3);
        __half2 h01 = __float22half2_rn(make_float2(v0, v1));
        __half2 h23 = __float22half2_rn(make_float2(v2, v3));
        *(uint2*)&dst[(tau0 + a) * 64 + hw0] =
            make_uint2(*(uint32_t*)&h01, *(uint32_t*)&h23);
    }
}

// ---------------------------------------------------------------------------
// k_gemm: BM=128, BN=128, BK=32, split-K=4. 256 threads = 8 warps (2m x 4n),
// warp tile 64x32. ONE __syncthreads per chunk; A 2-buf, B 3-buf.
// ---------------------------------------------------------------------------
#define ISSUE_B(K0, STOFF) do {                                              \
    uint32_t _st = sbase + (STOFF);                                          \
    _Pragma("unroll")                                                        \
    for (int _it = 0; _it < 2; _it++) {                                      \
        int _idx = tid + _it * 256;                                          \
        int _n = _idx >> 2, _seg = _idx & 3;                                 \
        cp16(_st + _n * ROWB + _seg * 16,                                    \
             WB + (size_t)_n * KDIM + (K0) + _seg * 8);                      \
    }                                                                        \
    asm volatile("cp.async.commit_group;" ::: "memory");                     \
} while (0)

#define LDG_A(K0) do {                                                       \
    _Pragma("unroll")                                                        \
    for (int _it = 0; _it < 4; _it++) {                                      \
        int _idx = tid + _it * 256;                                          \
        int _row = _idx >> 3, _seg = _idx & 7;                               \
        areg[_it] = *(const float4*)(Abase +                                 \
            (size_t)_row * (SW_DIM * KDIM) + (K0) + _seg * 4);               \
    }                                                                        \
} while (0)

#define STS_A(STOFF) do {                                                    \
    char* _pb = sm + (STOFF);                                                \
    _Pragma("unroll")                                                        \
    for (int _it = 0; _it < 4; _it++) {                                      \
        int _idx = tid + _it * 256;                                          \
        int _row = _idx >> 3, _seg = _idx & 7;                               \
        float4 _v = areg[_it];                                               \
        __half2 _h01 = __float22half2_rn(make_float2(_v.x, _v.y));           \
        __half2 _h23 = __float22half2_rn(make_float2(_v.z, _v.w));           \
        *(uint2*)(_pb + _row * ROWB + _seg * 8) =                            \
            make_uint2(*(uint32_t*)&_h01, *(uint32_t*)&_h23);                \
    }                                                                        \
} while (0)

__global__ void __launch_bounds__(256, 2)
k_gemm(const float* __restrict__ x) {
    extern __shared__ char sm[];
    const int tid = threadIdx.x;
    const int wid = tid >> 5, lid = tid & 31;
    const int s = blockIdx.x >> 2;
    const int ks = blockIdx.x & 3;
    const int m0 = blockIdx.y * BM;
    const int kbase = ks * KQ;
    const int wm = wid & 1, wn = wid >> 1;

    const uint32_t sbase = smem_u32(sm);
    const float* Abase = x + (size_t)m0 * (SW_DIM * KDIM) + (size_t)s * KDIM
                         + kbase;
    const __half* WB = g_W + (size_t)s * KF * KDIM + kbase;

    const int q = lid >> 3, r = lid & 7;
    const uint32_t laneA = (wm * 64 + (q & 1) * 8 + r) * ROWB + (q >> 1) * 16;
    const uint32_t laneB = (wn * 32 + (q >> 1) * 8 + r) * ROWB + (q & 1) * 16;

    float acc[4][4][4];
    #pragma unroll
    for (int a = 0; a < 4; a++)
        #pragma unroll
        for (int b = 0; b < 4; b++)
            #pragma unroll
            for (int c = 0; c < 4; c++) acc[a][b][c] = 0.f;

    float4 areg[4];

    // prologue: B(0), B(1) in flight; A(0) staged; areg = A(1)
    ISSUE_B(0, BOFF(0));
    ISSUE_B(BK, BOFF(1));
    LDG_A(0);
    STS_A(AOFF(0));
    LDG_A(BK);
    asm volatile("cp.async.wait_group 1;" ::: "memory");
    __syncthreads();

    for (int i = 0; i < NCHUNK; i++) {
        // refill the B buffer read in iter i-1 (safe post-sync)
        if (i + 2 < NCHUNK) ISSUE_B((i + 2) * BK, BOFF((i + 2) % 3));

        const uint32_t stA = sbase + AOFF(i & 1);
        const uint32_t stB = sbase + BOFF(i % 3);
        #pragma unroll
        for (int kk = 0; kk < 2; kk++) {
            const uint32_t ka = kk * 32;
            uint32_t Af[4][4], B0[4], B1[4];
            ldsm4(B0, stB + laneB + ka);
            ldsm4(B1, stB + laneB + ka + 16 * ROWB);
            #pragma unroll
            for (int mf = 0; mf < 4; mf++)
                ldsm4(Af[mf], stA + laneA + mf * (16 * ROWB) + ka);
            #pragma unroll
            for (int mf = 0; mf < 4; mf++) {
                #pragma unroll
                for (int nf = 0; nf < 4; nf++) {
                    const uint32_t* bb = ((nf & 2) ? B1 : B0) + (nf & 1) * 2;
                    mma_f16(acc[mf][nf], Af[mf], bb);
                }
            }
        }

        // stage A(i+1) into the other buffer (read last in iter i-1)
        if (i + 1 < NCHUNK) STS_A(AOFF((i + 1) & 1));
        if (i + 2 < NCHUNK) {
            LDG_A((i + 2) * BK);
            asm volatile("cp.async.wait_group 1;" ::: "memory");
        } else {
            asm volatile("cp.async.wait_group 0;" ::: "memory");
        }
        __syncthreads();
    }

    // write fp32 partial (no bias/relu)
    const int g = lid >> 2, tc = lid & 3;
    float* pbase = &g_part[ks][0][0];
    #pragma unroll
    for (int mf = 0; mf < 4; mf++) {
        const int row = m0 + wm * 64 + mf * 16 + g;
        #pragma unroll
        for (int nf = 0; nf < 4; nf++) {
            const int col = s * KF + wn * 32 + nf * 8 + tc * 2;
            *(float2*)&pbase[(size_t)row * OUTC + col] =
                make_float2(acc[mf][nf][0], acc[mf][nf][1]);
            *(float2*)&pbase[(size_t)(row + 8) * OUTC + col] =
                make_float2(acc[mf][nf][2], acc[mf][nf][3]);
        }
    }
}

// ---------------------------------------------------------------------------
// finalize: out = leaky(p0+p1+p2+p3 + bias); 2 float4 per thread
// ---------------------------------------------------------------------------
__global__ void __launch_bounds__(256)
k_fin(const float* __restrict__ bias, float* __restrict__ out) {
    #pragma unroll
    for (int u = 0; u < 2; u++) {
        int i = (blockIdx.x * 2 + u) * 256 + threadIdx.x;   // float4 index
        float4 a = *(const float4*)(&g_part[0][0][0] + (size_t)i * 4);
        float4 b = *(const float4*)(&g_part[1][0][0] + (size_t)i * 4);
        float4 c = *(const float4*)(&g_part[2][0][0] + (size_t)i * 4);
        float4 d = *(const float4*)(&g_part[3][0][0] + (size_t)i * 4);
        int col = (i * 4) & (OUTC - 1);
        float4 bb = *(const float4*)&bias[col];
        float v0 = (a.x + b.x) + (c.x + d.x) + bb.x;
        float v1 = (a.y + b.y) + (c.y + d.y) + bb.y;
        float v2 = (a.z + b.z) + (c.z + d.z) + bb.z;
        float v3 = (a.w + b.w) + (c.w + d.w) + bb.w;
        v0 = v0 > 0.f ? v0 : 0.01f * v0;
        v1 = v1 > 0.f ? v1 : 0.01f * v1;
        v2 = v2 > 0.f ? v2 : 0.01f * v2;
        v3 = v3 > 0.f ? v3 : 0.01f * v3;
        *(float4*)&out[(size_t)i * 4] = make_float4(v0, v1, v2, v3);
    }
}

// ---------------------------------------------------------------------------
extern "C" void kernel_launch(void* const* d_in, const int* in_sizes, int n_in,
                              void* d_out, int out_size) {
    const float* x    = (const float*)d_in[0];   // [2048,1,256,8,8]
    const float* cw   = (const float*)d_in[1];   // [4,128,84,8,8]
    const float* bias = (const float*)d_in[2];   // [4,128]
    float* out = (float*)d_out;                  // [2048,512]

    cudaFuncSetAttribute(k_weff, cudaFuncAttributeMaxDynamicSharedMemorySize,
                         WEFF_SMEM);
    cudaFuncSetAttribute(k_gemm, cudaFuncAttributeMaxDynamicSharedMemorySize,
                         DSMEM);

    k_mbuild<<<1, 256>>>();
    k_weff<<<SW_DIM * KF, 256, WEFF_SMEM>>>(cw);
    dim3 grid(SW_DIM * KSPLIT, B_DIM / BM);
    k_gemm<<<grid, 256, DSMEM>>>(x);
    k_fin<<<(B_DIM * OUTC / 8) / 256, 256>>>(bias, out);
}